// round 1
// baseline (speedup 1.0000x reference)
#include <cuda_runtime.h>
#include <cuda_bf16.h>
#include <cstddef>

// Problem constants
#define BB 2
#define TT 2048
#define DD 1024
#define HH 16
#define HD 64
#define WIN 16
#define NG 128          // T/stride global keys
#define D3 3072         // qkv row stride

// Scratch (allocation-free rule: __device__ globals)
__device__ float g_qkv[(size_t)BB * TT * D3];     // [B*T, 3*D]
__device__ float g_attn[(size_t)BB * TT * DD];    // [B*T, D]

// ---------------------------------------------------------------------------
// SGEMM: C[M,N] = A[M,K] @ B[K,N] (+bias). 128x128 block, 8x8 per thread.
// ---------------------------------------------------------------------------
__global__ __launch_bounds__(256, 2)
void sgemm128(const float* __restrict__ A, const float* __restrict__ B,
              float* __restrict__ C, int M, int N, int K,
              const float* __restrict__ bias)
{
    __shared__ float As[8][128];
    __shared__ float Bs[8][128];

    const int tid  = threadIdx.x;
    const int cRow = blockIdx.y * 128;
    const int cCol = blockIdx.x * 128;
    const int tx = tid & 15;       // 0..15 -> col group
    const int ty = tid >> 4;       // 0..15 -> row group

    const int aRow = tid >> 1;            // 0..127
    const int aCol = (tid & 1) * 4;       // 0 or 4
    const int bRow = tid >> 5;            // 0..7
    const int bCol = (tid & 31) * 4;      // 0..124

    const float* Aptr = A + (size_t)(cRow + aRow) * K + aCol;
    const float* Bptr = B + (size_t)bRow * N + cCol + bCol;

    float acc[8][8];
    #pragma unroll
    for (int i = 0; i < 8; ++i)
        #pragma unroll
        for (int j = 0; j < 8; ++j) acc[i][j] = 0.f;

    for (int k0 = 0; k0 < K; k0 += 8) {
        float4 av = *(const float4*)(Aptr + k0);
        float4 bv = *(const float4*)(Bptr + (size_t)k0 * N);
        As[aCol + 0][aRow] = av.x;
        As[aCol + 1][aRow] = av.y;
        As[aCol + 2][aRow] = av.z;
        As[aCol + 3][aRow] = av.w;
        *(float4*)&Bs[bRow][bCol] = bv;
        __syncthreads();

        #pragma unroll
        for (int k = 0; k < 8; ++k) {
            float ra[8], rb[8];
            #pragma unroll
            for (int i = 0; i < 8; ++i) ra[i] = As[k][ty * 8 + i];
            #pragma unroll
            for (int j = 0; j < 8; ++j) rb[j] = Bs[k][tx * 8 + j];
            #pragma unroll
            for (int i = 0; i < 8; ++i)
                #pragma unroll
                for (int j = 0; j < 8; ++j)
                    acc[i][j] += ra[i] * rb[j];
        }
        __syncthreads();
    }

    float bj[8];
    #pragma unroll
    for (int j = 0; j < 8; ++j)
        bj[j] = bias ? bias[cCol + tx * 8 + j] : 0.f;

    #pragma unroll
    for (int i = 0; i < 8; ++i) {
        const size_t r = (size_t)(cRow + ty * 8 + i) * N + cCol + tx * 8;
        float4 o0, o1;
        o0.x = acc[i][0] + bj[0]; o0.y = acc[i][1] + bj[1];
        o0.z = acc[i][2] + bj[2]; o0.w = acc[i][3] + bj[3];
        o1.x = acc[i][4] + bj[4]; o1.y = acc[i][5] + bj[5];
        o1.z = acc[i][6] + bj[6]; o1.w = acc[i][7] + bj[7];
        *(float4*)&C[r]     = o0;
        *(float4*)&C[r + 4] = o1;
    }
}

// ---------------------------------------------------------------------------
// Fused sparse attention. One block = (b, h, 64-query tile). 256 threads.
// Local window-16 (zero-padded keys INCLUDED in softmax, matching reference
// zero-pad) + 128 strided global keys, independent softmaxes, summed.
// ---------------------------------------------------------------------------
#define PAD 68           // row stride in floats (64 + 4) -> conflict-free LDS.128
#define TQ 64
// smem: Q 64 rows, Kg/Vg 128 rows, Kl/Vl 80 rows
#define SMEM_FLOATS (64*PAD + 2*128*PAD + 2*80*PAD)

__global__ __launch_bounds__(256, 1)
void attn_kernel(const float* __restrict__ qkv, float* __restrict__ out)
{
    const int t0 = blockIdx.x * TQ;
    const int h  = blockIdx.y;
    const int b  = blockIdx.z;
    const int tid = threadIdx.x;

    extern __shared__ float smem[];
    float* sQ  = smem;                 // [64][PAD]
    float* sKg = sQ  + 64 * PAD;       // [128][PAD]
    float* sVg = sKg + 128 * PAD;      // [128][PAD]
    float* sKl = sVg + 128 * PAD;      // [80][PAD]
    float* sVl = sKl + 80 * PAD;       // [80][PAD]

    const size_t baseBT = (size_t)b * TT;
    const int hoff = h * HD;

    // ---- stage tiles ----
    for (int idx = tid; idx < 64 * 16; idx += 256) {
        const int r = idx >> 4, c4 = (idx & 15) * 4;
        const float4 v = *(const float4*)&qkv[(baseBT + t0 + r) * D3 + hoff + c4];
        *(float4*)&sQ[r * PAD + c4] = v;
    }
    for (int idx = tid; idx < 128 * 16; idx += 256) {
        const int r = idx >> 4, c4 = (idx & 15) * 4;
        const size_t ro = (baseBT + r * 16) * D3 + hoff + c4;
        *(float4*)&sKg[r * PAD + c4] = *(const float4*)&qkv[ro + 1024];
        *(float4*)&sVg[r * PAD + c4] = *(const float4*)&qkv[ro + 2048];
    }
    for (int idx = tid; idx < 80 * 16; idx += 256) {
        const int r = idx >> 4, c4 = (idx & 15) * 4;
        const int t = t0 - 15 + r;
        float4 kv = make_float4(0.f, 0.f, 0.f, 0.f);
        float4 vv = kv;
        if (r < 79 && t >= 0 && t < TT) {
            const size_t ro = (baseBT + t) * D3 + hoff + c4;
            kv = *(const float4*)&qkv[ro + 1024];
            vv = *(const float4*)&qkv[ro + 2048];
        }
        *(float4*)&sKl[r * PAD + c4] = kv;
        *(float4*)&sVl[r * PAD + c4] = vv;
    }
    __syncthreads();

    const int warp = tid >> 5;
    const int lane = tid & 31;
    const float scale = 0.125f;   // 1/sqrt(64)

    for (int i = 0; i < 8; ++i) {
        const int qi = warp * 8 + i;        // local query row (0..63)
        const int t  = t0 + qi;
        const float* qrow = &sQ[qi * PAD];

        // ---- global scores: lane owns keys {lane, lane+32, lane+64, lane+96}
        float sg[4] = {0.f, 0.f, 0.f, 0.f};
        // ---- local score: lane (mod 16) owns window slot (lane&15)
        const int lrow = qi + (lane & 15);  // row in sKl for window slot
        float sl = 0.f;
        #pragma unroll
        for (int d4 = 0; d4 < 16; ++d4) {
            const float4 qv = *(const float4*)&qrow[d4 * 4];
            #pragma unroll
            for (int c = 0; c < 4; ++c) {
                const float4 kv = *(const float4*)&sKg[(lane + c * 32) * PAD + d4 * 4];
                sg[c] += qv.x * kv.x + qv.y * kv.y + qv.z * kv.z + qv.w * kv.w;
            }
            const float4 kl = *(const float4*)&sKl[lrow * PAD + d4 * 4];
            sl += qv.x * kl.x + qv.y * kl.y + qv.z * kl.z + qv.w * kl.w;
        }
        sl *= scale;
        #pragma unroll
        for (int c = 0; c < 4; ++c) sg[c] *= scale;

        // ---- local softmax over 16 slots (both 16-lane halves identical)
        float ml = sl;
        #pragma unroll
        for (int o = 8; o >= 1; o >>= 1)
            ml = fmaxf(ml, __shfl_xor_sync(0xffffffffu, ml, o, 16));
        const float el = __expf(sl - ml);
        float suml = el;
        #pragma unroll
        for (int o = 8; o >= 1; o >>= 1)
            suml += __shfl_xor_sync(0xffffffffu, suml, o, 16);
        const float pl = el / suml;

        // ---- global softmax over 128
        float mg = fmaxf(fmaxf(sg[0], sg[1]), fmaxf(sg[2], sg[3]));
        #pragma unroll
        for (int o = 16; o >= 1; o >>= 1)
            mg = fmaxf(mg, __shfl_xor_sync(0xffffffffu, mg, o));
        float eg[4], sumg = 0.f;
        #pragma unroll
        for (int c = 0; c < 4; ++c) { eg[c] = __expf(sg[c] - mg); sumg += eg[c]; }
        #pragma unroll
        for (int o = 16; o >= 1; o >>= 1)
            sumg += __shfl_xor_sync(0xffffffffu, sumg, o);
        const float inv_sumg = 1.f / sumg;

        // ---- AV: lane owns output dims {lane, lane+32}
        float a0 = 0.f, a1 = 0.f;
        #pragma unroll
        for (int j = 0; j < 16; ++j) {
            const float pj = __shfl_sync(0xffffffffu, pl, j);
            const float* vr = &sVl[(qi + j) * PAD];
            a0 += pj * vr[lane];
            a1 += pj * vr[lane + 32];
        }
        #pragma unroll
        for (int c = 0; c < 4; ++c) {
            const float pc = eg[c] * inv_sumg;
            #pragma unroll 8
            for (int jj = 0; jj < 32; ++jj) {
                const float pj = __shfl_sync(0xffffffffu, pc, jj);
                const float* vr = &sVg[(c * 32 + jj) * PAD];
                a0 += pj * vr[lane];
                a1 += pj * vr[lane + 32];
            }
        }

        float* orow = &out[(baseBT + t) * DD + hoff];
        orow[lane]      = a0;
        orow[lane + 32] = a1;
    }
}

// ---------------------------------------------------------------------------
extern "C" void kernel_launch(void* const* d_in, const int* in_sizes, int n_in,
                              void* d_out, int out_size)
{
    const float* x      = (const float*)d_in[0];
    const float* w_qkv  = (const float*)d_in[1];
    const float* w_proj = (const float*)d_in[2];
    const float* b_proj = (const float*)d_in[3];
    float* out = (float*)d_out;

    float* qkv;  float* attn;
    cudaGetSymbolAddress((void**)&qkv,  g_qkv);
    cudaGetSymbolAddress((void**)&attn, g_attn);

    const int M = BB * TT;   // 4096
    const size_t smem_bytes = SMEM_FLOATS * sizeof(float);
    cudaFuncSetAttribute(attn_kernel,
                         cudaFuncAttributeMaxDynamicSharedMemorySize,
                         (int)smem_bytes);

    // 1) qkv = x @ w_qkv
    sgemm128<<<dim3(D3 / 128, M / 128), 256>>>(x, w_qkv, qkv, M, D3, DD, nullptr);

    // 2) fused sparse attention -> [B*T, D]
    attn_kernel<<<dim3(TT / TQ, HH, BB), 256, smem_bytes>>>(qkv, attn);

    // 3) out = attn @ w_proj + b_proj
    sgemm128<<<dim3(DD / 128, M / 128), 256>>>(attn, w_proj, out, M, DD, DD, b_proj);
}

// round 3
// speedup vs baseline: 1.7116x; 1.7116x over previous
#include <cuda_runtime.h>
#include <cuda_bf16.h>
#include <cstdint>
#include <cstddef>

// Problem constants
#define BB 2
#define TT 2048
#define DD 1024
#define HH 16
#define HD 64
#define D3 3072

// Scratch (allocation-free rule: __device__ globals)
__device__ float g_qkv[(size_t)BB * TT * D3];
__device__ float g_attn[(size_t)BB * TT * DD];

// ---------------------------------------------------------------------------
// MMA / ldmatrix helpers (baseline PTX features — no sm_103a-gated instrs)
// ---------------------------------------------------------------------------
__device__ __forceinline__ uint32_t smem_u32(const void* p) {
    uint32_t a;
    asm("{ .reg .u64 t; cvta.to.shared.u64 t, %1; cvt.u32.u64 %0, t; }"
        : "=r"(a) : "l"(p));
    return a;
}
__device__ __forceinline__ void ldsm_x4(uint32_t* r, uint32_t addr) {
    asm volatile("ldmatrix.sync.aligned.m8n8.x4.shared.b16 {%0,%1,%2,%3}, [%4];"
                 : "=r"(r[0]), "=r"(r[1]), "=r"(r[2]), "=r"(r[3]) : "r"(addr));
}
__device__ __forceinline__ void ldsm_x4_t(uint32_t* r, uint32_t addr) {
    asm volatile("ldmatrix.sync.aligned.m8n8.x4.trans.shared.b16 {%0,%1,%2,%3}, [%4];"
                 : "=r"(r[0]), "=r"(r[1]), "=r"(r[2]), "=r"(r[3]) : "r"(addr));
}
__device__ __forceinline__ void mma_bf16(float* d, const uint32_t* a, const uint32_t* b) {
    asm volatile("mma.sync.aligned.m16n8k16.row.col.f32.bf16.bf16.f32 "
                 "{%0,%1,%2,%3}, {%4,%5,%6,%7}, {%8,%9}, {%0,%1,%2,%3};"
                 : "+f"(d[0]), "+f"(d[1]), "+f"(d[2]), "+f"(d[3])
                 : "r"(a[0]), "r"(a[1]), "r"(a[2]), "r"(a[3]),
                   "r"(b[0]), "r"(b[1]));
}

// ---------------------------------------------------------------------------
// bf16-split GEMM: C[M,N] = A[M,K] @ W[K,N] (+bias)
// A = Ah + Al (bf16), W = Wh + Wl (bf16); C ≈ Ah·Wh + Ah·Wl + Al·Wh
// CTA tile 128x128, 8 warps of 64x32, K-chunk 32, double-buffered SMEM.
// ---------------------------------------------------------------------------
#define A_STRIDE 40                       // bf16 elems per A row (64B + pad)
#define B_STRIDE 136                      // bf16 elems per B row (256B + pad)
#define A_BYTES  (128 * A_STRIDE * 2)     // 10240
#define B_BYTES  (32 * B_STRIDE * 2)      // 8704
#define STAGE_BYTES (2 * A_BYTES + 2 * B_BYTES)   // 37888
#define GEMM_SMEM   (2 * STAGE_BYTES)             // 75776

__device__ __forceinline__ void cvt8(const float4 v, uint2& hi, uint2& lo) {
    __nv_bfloat162 h0 = __floats2bfloat162_rn(v.x, v.y);
    __nv_bfloat162 h1 = __floats2bfloat162_rn(v.z, v.w);
    __nv_bfloat162 l0 = __floats2bfloat162_rn(v.x - __bfloat162float(h0.x),
                                              v.y - __bfloat162float(h0.y));
    __nv_bfloat162 l1 = __floats2bfloat162_rn(v.z - __bfloat162float(h1.x),
                                              v.w - __bfloat162float(h1.y));
    hi.x = *(uint32_t*)&h0; hi.y = *(uint32_t*)&h1;
    lo.x = *(uint32_t*)&l0; lo.y = *(uint32_t*)&l1;
}

__device__ __forceinline__ void store_stage(char* st, const float4* ra, const float4* rb,
                                            int ar, int ah, int br, int bc)
{
    char* aH = st;
    char* aL = st + A_BYTES;
    char* bH = st + 2 * A_BYTES;
    char* bL = st + 2 * A_BYTES + B_BYTES;
    #pragma unroll
    for (int i = 0; i < 4; ++i) {
        uint2 hi, lo;
        cvt8(ra[i], hi, lo);
        const int off = (ar * A_STRIDE + ah * 16 + i * 4) * 2;
        *(uint2*)(aH + off) = hi;
        *(uint2*)(aL + off) = lo;
    }
    #pragma unroll
    for (int i = 0; i < 4; ++i) {
        uint2 hi, lo;
        cvt8(rb[i], hi, lo);
        const int off = (br * B_STRIDE + bc + i * 4) * 2;
        *(uint2*)(bH + off) = hi;
        *(uint2*)(bL + off) = lo;
    }
}

__global__ __launch_bounds__(256, 1)
void gemm_bf16x3(const float* __restrict__ A, const float* __restrict__ W,
                 float* __restrict__ C, int M, int N, int K,
                 const float* __restrict__ bias)
{
    extern __shared__ char sm[];
    const uint32_t sb = smem_u32(sm);
    const int tid = threadIdx.x;
    const int lane = tid & 31, wid = tid >> 5;
    const int wm = wid & 1, wn = wid >> 1;      // warp grid 2 (m) x 4 (n)
    const int m0 = blockIdx.y * 128, n0 = blockIdx.x * 128;
    const int NC = K >> 5;

    // staging roles
    const int ar = tid >> 1, ah = tid & 1;        // A: row 0..127, 16-col half
    const int br = tid >> 3, bc = (tid & 7) * 16; // B: k-row 0..31, 16-col group

    const float* Ap = A + (size_t)(m0 + ar) * K + ah * 16;
    const float* Wp = W + (size_t)br * N + n0 + bc;

    float acc[4][4][4];
    #pragma unroll
    for (int mt = 0; mt < 4; ++mt)
        #pragma unroll
        for (int nt = 0; nt < 4; ++nt)
            #pragma unroll
            for (int q = 0; q < 4; ++q) acc[mt][nt][q] = 0.f;

    float4 ra[4], rb[4];
    #pragma unroll
    for (int i = 0; i < 4; ++i) ra[i] = *(const float4*)(Ap + i * 4);
    #pragma unroll
    for (int i = 0; i < 4; ++i) rb[i] = *(const float4*)(Wp + i * 4);
    store_stage(sm, ra, rb, ar, ah, br, bc);
    __syncthreads();

    // per-warp ldmatrix base addresses (within a stage)
    const uint32_t aRow = ((wm * 64 + (lane & 15)) * A_STRIDE + (lane >> 4) * 8) * 2;
    const int km = (lane & 7) + ((lane >> 3) & 1) * 8;
    const uint32_t bCol = 2 * A_BYTES + (km * B_STRIDE + wn * 32 + (lane >> 4) * 8) * 2;

    for (int c = 0; c < NC; ++c) {
        const int s = c & 1;
        if (c + 1 < NC) {
            #pragma unroll
            for (int i = 0; i < 4; ++i)
                ra[i] = *(const float4*)(Ap + (c + 1) * 32 + i * 4);
            #pragma unroll
            for (int i = 0; i < 4; ++i)
                rb[i] = *(const float4*)(Wp + (size_t)(c + 1) * 32 * N + i * 4);
        }

        const uint32_t stb = sb + (uint32_t)s * STAGE_BYTES;
        #pragma unroll
        for (int ks = 0; ks < 2; ++ks) {
            const int k0 = ks * 16;
            uint32_t ahr[4][4], alr[4][4];
            #pragma unroll
            for (int mt = 0; mt < 4; ++mt) {
                ldsm_x4(ahr[mt], stb + aRow + (mt * 16 * A_STRIDE + k0) * 2);
                ldsm_x4(alr[mt], stb + A_BYTES + aRow + (mt * 16 * A_STRIDE + k0) * 2);
            }
            uint32_t bh[8], bl[8];
            ldsm_x4_t(bh,     stb + bCol + (k0 * B_STRIDE) * 2);
            ldsm_x4_t(bh + 4, stb + bCol + (k0 * B_STRIDE + 16) * 2);
            ldsm_x4_t(bl,     stb + B_BYTES + bCol + (k0 * B_STRIDE) * 2);
            ldsm_x4_t(bl + 4, stb + B_BYTES + bCol + (k0 * B_STRIDE + 16) * 2);
            #pragma unroll
            for (int mt = 0; mt < 4; ++mt)
                #pragma unroll
                for (int nt = 0; nt < 4; ++nt) {
                    mma_bf16(acc[mt][nt], ahr[mt], bh + nt * 2);
                    mma_bf16(acc[mt][nt], ahr[mt], bl + nt * 2);
                    mma_bf16(acc[mt][nt], alr[mt], bh + nt * 2);
                }
        }

        if (c + 1 < NC)
            store_stage(sm + (s ^ 1) * STAGE_BYTES, ra, rb, ar, ah, br, bc);
        __syncthreads();
    }

    // epilogue
    const int row = m0 + wm * 64 + (lane >> 2);
    const int col0 = n0 + wn * 32 + (lane & 3) * 2;
    #pragma unroll
    for (int nt = 0; nt < 4; ++nt) {
        float2 bv = make_float2(0.f, 0.f);
        if (bias) bv = *(const float2*)(bias + col0 + nt * 8);
        #pragma unroll
        for (int mt = 0; mt < 4; ++mt) {
            const float* d = acc[mt][nt];
            float2 o0 = make_float2(d[0] + bv.x, d[1] + bv.y);
            float2 o1 = make_float2(d[2] + bv.x, d[3] + bv.y);
            *(float2*)&C[(size_t)(row + mt * 16) * N + col0 + nt * 8] = o0;
            *(float2*)&C[(size_t)(row + mt * 16 + 8) * N + col0 + nt * 8] = o1;
        }
    }
}

// ---------------------------------------------------------------------------
// Fused sparse attention (unchanged from passing R1 version).
// ---------------------------------------------------------------------------
#define PAD 68
#define TQ 64
#define SMEM_FLOATS (64*PAD + 2*128*PAD + 2*80*PAD)

__global__ __launch_bounds__(256, 1)
void attn_kernel(const float* __restrict__ qkv, float* __restrict__ out)
{
    const int t0 = blockIdx.x * TQ;
    const int h  = blockIdx.y;
    const int b  = blockIdx.z;
    const int tid = threadIdx.x;

    extern __shared__ float smemf[];
    float* sQ  = smemf;
    float* sKg = sQ  + 64 * PAD;
    float* sVg = sKg + 128 * PAD;
    float* sKl = sVg + 128 * PAD;
    float* sVl = sKl + 80 * PAD;

    const size_t baseBT = (size_t)b * TT;
    const int hoff = h * HD;

    for (int idx = tid; idx < 64 * 16; idx += 256) {
        const int r = idx >> 4, c4 = (idx & 15) * 4;
        const float4 v = *(const float4*)&qkv[(baseBT + t0 + r) * D3 + hoff + c4];
        *(float4*)&sQ[r * PAD + c4] = v;
    }
    for (int idx = tid; idx < 128 * 16; idx += 256) {
        const int r = idx >> 4, c4 = (idx & 15) * 4;
        const size_t ro = (baseBT + r * 16) * D3 + hoff + c4;
        *(float4*)&sKg[r * PAD + c4] = *(const float4*)&qkv[ro + 1024];
        *(float4*)&sVg[r * PAD + c4] = *(const float4*)&qkv[ro + 2048];
    }
    for (int idx = tid; idx < 80 * 16; idx += 256) {
        const int r = idx >> 4, c4 = (idx & 15) * 4;
        const int t = t0 - 15 + r;
        float4 kv = make_float4(0.f, 0.f, 0.f, 0.f);
        float4 vv = kv;
        if (r < 79 && t >= 0 && t < TT) {
            const size_t ro = (baseBT + t) * D3 + hoff + c4;
            kv = *(const float4*)&qkv[ro + 1024];
            vv = *(const float4*)&qkv[ro + 2048];
        }
        *(float4*)&sKl[r * PAD + c4] = kv;
        *(float4*)&sVl[r * PAD + c4] = vv;
    }
    __syncthreads();

    const int warp = tid >> 5;
    const int lane = tid & 31;
    const float scale = 0.125f;

    for (int i = 0; i < 8; ++i) {
        const int qi = warp * 8 + i;
        const int t  = t0 + qi;
        const float* qrow = &sQ[qi * PAD];

        float sg[4] = {0.f, 0.f, 0.f, 0.f};
        const int lrow = qi + (lane & 15);
        float sl = 0.f;
        #pragma unroll
        for (int d4 = 0; d4 < 16; ++d4) {
            const float4 qv = *(const float4*)&qrow[d4 * 4];
            #pragma unroll
            for (int c = 0; c < 4; ++c) {
                const float4 kv = *(const float4*)&sKg[(lane + c * 32) * PAD + d4 * 4];
                sg[c] += qv.x * kv.x + qv.y * kv.y + qv.z * kv.z + qv.w * kv.w;
            }
            const float4 kl = *(const float4*)&sKl[lrow * PAD + d4 * 4];
            sl += qv.x * kl.x + qv.y * kl.y + qv.z * kl.z + qv.w * kl.w;
        }
        sl *= scale;
        #pragma unroll
        for (int c = 0; c < 4; ++c) sg[c] *= scale;

        float ml = sl;
        #pragma unroll
        for (int o = 8; o >= 1; o >>= 1)
            ml = fmaxf(ml, __shfl_xor_sync(0xffffffffu, ml, o, 16));
        const float el = __expf(sl - ml);
        float suml = el;
        #pragma unroll
        for (int o = 8; o >= 1; o >>= 1)
            suml += __shfl_xor_sync(0xffffffffu, suml, o, 16);
        const float pl = el / suml;

        float mg = fmaxf(fmaxf(sg[0], sg[1]), fmaxf(sg[2], sg[3]));
        #pragma unroll
        for (int o = 16; o >= 1; o >>= 1)
            mg = fmaxf(mg, __shfl_xor_sync(0xffffffffu, mg, o));
        float eg[4], sumg = 0.f;
        #pragma unroll
        for (int c = 0; c < 4; ++c) { eg[c] = __expf(sg[c] - mg); sumg += eg[c]; }
        #pragma unroll
        for (int o = 16; o >= 1; o >>= 1)
            sumg += __shfl_xor_sync(0xffffffffu, sumg, o);
        const float inv_sumg = 1.f / sumg;

        float a0 = 0.f, a1 = 0.f;
        #pragma unroll
        for (int j = 0; j < 16; ++j) {
            const float pj = __shfl_sync(0xffffffffu, pl, j);
            const float* vr = &sVl[(qi + j) * PAD];
            a0 += pj * vr[lane];
            a1 += pj * vr[lane + 32];
        }
        #pragma unroll
        for (int c = 0; c < 4; ++c) {
            const float pc = eg[c] * inv_sumg;
            #pragma unroll 8
            for (int jj = 0; jj < 32; ++jj) {
                const float pj = __shfl_sync(0xffffffffu, pc, jj);
                const float* vr = &sVg[(c * 32 + jj) * PAD];
                a0 += pj * vr[lane];
                a1 += pj * vr[lane + 32];
            }
        }

        float* orow = &out[(baseBT + t) * DD + hoff];
        orow[lane]      = a0;
        orow[lane + 32] = a1;
    }
}

// ---------------------------------------------------------------------------
extern "C" void kernel_launch(void* const* d_in, const int* in_sizes, int n_in,
                              void* d_out, int out_size)
{
    const float* x      = (const float*)d_in[0];
    const float* w_qkv  = (const float*)d_in[1];
    const float* w_proj = (const float*)d_in[2];
    const float* b_proj = (const float*)d_in[3];
    float* out = (float*)d_out;

    float *qkv, *attn;
    cudaGetSymbolAddress((void**)&qkv,  g_qkv);
    cudaGetSymbolAddress((void**)&attn, g_attn);

    const int M = BB * TT;  // 4096

    cudaFuncSetAttribute(gemm_bf16x3, cudaFuncAttributeMaxDynamicSharedMemorySize, GEMM_SMEM);
    const size_t attn_smem = SMEM_FLOATS * sizeof(float);
    cudaFuncSetAttribute(attn_kernel, cudaFuncAttributeMaxDynamicSharedMemorySize, (int)attn_smem);

    // 1) qkv = x @ w_qkv   (bf16-split tensor cores, no weight transpose needed)
    gemm_bf16x3<<<dim3(D3 / 128, M / 128), 256, GEMM_SMEM>>>(x, w_qkv, qkv, M, D3, DD, nullptr);

    // 2) fused sparse attention
    attn_kernel<<<dim3(TT / TQ, HH, BB), 256, attn_smem>>>(qkv, attn);

    // 3) out = attn @ w_proj + b_proj
    gemm_bf16x3<<<dim3(DD / 128, M / 128), 256, GEMM_SMEM>>>(attn, w_proj, out, M, DD, DD, b_proj);
}

// round 4
// speedup vs baseline: 2.3216x; 1.3564x over previous
#include <cuda_runtime.h>
#include <cuda_bf16.h>
#include <cstdint>
#include <cstddef>

// Problem constants
#define BB 2
#define TT 2048
#define DD 1024
#define HH 16
#define HD 64
#define D3 3072

// Scratch (allocation-free rule: __device__ globals)
__device__ float g_qkv[(size_t)BB * TT * D3];
__device__ float g_attn[(size_t)BB * TT * DD];

// ---------------------------------------------------------------------------
// MMA / ldmatrix helpers (baseline PTX features — no sm_103a-gated instrs)
// ---------------------------------------------------------------------------
__device__ __forceinline__ uint32_t smem_u32(const void* p) {
    uint32_t a;
    asm("{ .reg .u64 t; cvta.to.shared.u64 t, %1; cvt.u32.u64 %0, t; }"
        : "=r"(a) : "l"(p));
    return a;
}
__device__ __forceinline__ void ldsm_x4(uint32_t* r, uint32_t addr) {
    asm volatile("ldmatrix.sync.aligned.m8n8.x4.shared.b16 {%0,%1,%2,%3}, [%4];"
                 : "=r"(r[0]), "=r"(r[1]), "=r"(r[2]), "=r"(r[3]) : "r"(addr));
}
__device__ __forceinline__ void ldsm_x4_t(uint32_t* r, uint32_t addr) {
    asm volatile("ldmatrix.sync.aligned.m8n8.x4.trans.shared.b16 {%0,%1,%2,%3}, [%4];"
                 : "=r"(r[0]), "=r"(r[1]), "=r"(r[2]), "=r"(r[3]) : "r"(addr));
}
__device__ __forceinline__ void mma_bf16(float* d, const uint32_t* a, const uint32_t* b) {
    asm volatile("mma.sync.aligned.m16n8k16.row.col.f32.bf16.bf16.f32 "
                 "{%0,%1,%2,%3}, {%4,%5,%6,%7}, {%8,%9}, {%0,%1,%2,%3};"
                 : "+f"(d[0]), "+f"(d[1]), "+f"(d[2]), "+f"(d[3])
                 : "r"(a[0]), "r"(a[1]), "r"(a[2]), "r"(a[3]),
                   "r"(b[0]), "r"(b[1]));
}

// ---------------------------------------------------------------------------
// bf16-split GEMM (unchanged from R3 win): C = A @ W (+bias)
// ---------------------------------------------------------------------------
#define A_STRIDE 40
#define B_STRIDE 136
#define A_BYTES  (128 * A_STRIDE * 2)
#define B_BYTES  (32 * B_STRIDE * 2)
#define STAGE_BYTES (2 * A_BYTES + 2 * B_BYTES)
#define GEMM_SMEM   (2 * STAGE_BYTES)

__device__ __forceinline__ void cvt8(const float4 v, uint2& hi, uint2& lo) {
    __nv_bfloat162 h0 = __floats2bfloat162_rn(v.x, v.y);
    __nv_bfloat162 h1 = __floats2bfloat162_rn(v.z, v.w);
    __nv_bfloat162 l0 = __floats2bfloat162_rn(v.x - __bfloat162float(h0.x),
                                              v.y - __bfloat162float(h0.y));
    __nv_bfloat162 l1 = __floats2bfloat162_rn(v.z - __bfloat162float(h1.x),
                                              v.w - __bfloat162float(h1.y));
    hi.x = *(uint32_t*)&h0; hi.y = *(uint32_t*)&h1;
    lo.x = *(uint32_t*)&l0; lo.y = *(uint32_t*)&l1;
}

__device__ __forceinline__ void store_stage(char* st, const float4* ra, const float4* rb,
                                            int ar, int ah, int br, int bc)
{
    char* aH = st;
    char* aL = st + A_BYTES;
    char* bH = st + 2 * A_BYTES;
    char* bL = st + 2 * A_BYTES + B_BYTES;
    #pragma unroll
    for (int i = 0; i < 4; ++i) {
        uint2 hi, lo;
        cvt8(ra[i], hi, lo);
        const int off = (ar * A_STRIDE + ah * 16 + i * 4) * 2;
        *(uint2*)(aH + off) = hi;
        *(uint2*)(aL + off) = lo;
    }
    #pragma unroll
    for (int i = 0; i < 4; ++i) {
        uint2 hi, lo;
        cvt8(rb[i], hi, lo);
        const int off = (br * B_STRIDE + bc + i * 4) * 2;
        *(uint2*)(bH + off) = hi;
        *(uint2*)(bL + off) = lo;
    }
}

__global__ __launch_bounds__(256, 1)
void gemm_bf16x3(const float* __restrict__ A, const float* __restrict__ W,
                 float* __restrict__ C, int M, int N, int K,
                 const float* __restrict__ bias)
{
    extern __shared__ char sm[];
    const uint32_t sb = smem_u32(sm);
    const int tid = threadIdx.x;
    const int lane = tid & 31, wid = tid >> 5;
    const int wm = wid & 1, wn = wid >> 1;
    const int m0 = blockIdx.y * 128, n0 = blockIdx.x * 128;
    const int NC = K >> 5;

    const int ar = tid >> 1, ah = tid & 1;
    const int br = tid >> 3, bc = (tid & 7) * 16;

    const float* Ap = A + (size_t)(m0 + ar) * K + ah * 16;
    const float* Wp = W + (size_t)br * N + n0 + bc;

    float acc[4][4][4];
    #pragma unroll
    for (int mt = 0; mt < 4; ++mt)
        #pragma unroll
        for (int nt = 0; nt < 4; ++nt)
            #pragma unroll
            for (int q = 0; q < 4; ++q) acc[mt][nt][q] = 0.f;

    float4 ra[4], rb[4];
    #pragma unroll
    for (int i = 0; i < 4; ++i) ra[i] = *(const float4*)(Ap + i * 4);
    #pragma unroll
    for (int i = 0; i < 4; ++i) rb[i] = *(const float4*)(Wp + i * 4);
    store_stage(sm, ra, rb, ar, ah, br, bc);
    __syncthreads();

    const uint32_t aRow = ((wm * 64 + (lane & 15)) * A_STRIDE + (lane >> 4) * 8) * 2;
    const int km = (lane & 7) + ((lane >> 3) & 1) * 8;
    const uint32_t bCol = 2 * A_BYTES + (km * B_STRIDE + wn * 32 + (lane >> 4) * 8) * 2;

    for (int c = 0; c < NC; ++c) {
        const int s = c & 1;
        if (c + 1 < NC) {
            #pragma unroll
            for (int i = 0; i < 4; ++i)
                ra[i] = *(const float4*)(Ap + (c + 1) * 32 + i * 4);
            #pragma unroll
            for (int i = 0; i < 4; ++i)
                rb[i] = *(const float4*)(Wp + (size_t)(c + 1) * 32 * N + i * 4);
        }

        const uint32_t stb = sb + (uint32_t)s * STAGE_BYTES;
        #pragma unroll
        for (int ks = 0; ks < 2; ++ks) {
            const int k0 = ks * 16;
            uint32_t ahr[4][4], alr[4][4];
            #pragma unroll
            for (int mt = 0; mt < 4; ++mt) {
                ldsm_x4(ahr[mt], stb + aRow + (mt * 16 * A_STRIDE + k0) * 2);
                ldsm_x4(alr[mt], stb + A_BYTES + aRow + (mt * 16 * A_STRIDE + k0) * 2);
            }
            uint32_t bh[8], bl[8];
            ldsm_x4_t(bh,     stb + bCol + (k0 * B_STRIDE) * 2);
            ldsm_x4_t(bh + 4, stb + bCol + (k0 * B_STRIDE + 16) * 2);
            ldsm_x4_t(bl,     stb + B_BYTES + bCol + (k0 * B_STRIDE) * 2);
            ldsm_x4_t(bl + 4, stb + B_BYTES + bCol + (k0 * B_STRIDE + 16) * 2);
            #pragma unroll
            for (int mt = 0; mt < 4; ++mt)
                #pragma unroll
                for (int nt = 0; nt < 4; ++nt) {
                    mma_bf16(acc[mt][nt], ahr[mt], bh + nt * 2);
                    mma_bf16(acc[mt][nt], ahr[mt], bl + nt * 2);
                    mma_bf16(acc[mt][nt], alr[mt], bh + nt * 2);
                }
        }

        if (c + 1 < NC)
            store_stage(sm + (s ^ 1) * STAGE_BYTES, ra, rb, ar, ah, br, bc);
        __syncthreads();
    }

    const int row = m0 + wm * 64 + (lane >> 2);
    const int col0 = n0 + wn * 32 + (lane & 3) * 2;
    #pragma unroll
    for (int nt = 0; nt < 4; ++nt) {
        float2 bv = make_float2(0.f, 0.f);
        if (bias) bv = *(const float2*)(bias + col0 + nt * 8);
        #pragma unroll
        for (int mt = 0; mt < 4; ++mt) {
            const float* d = acc[mt][nt];
            float2 o0 = make_float2(d[0] + bv.x, d[1] + bv.y);
            float2 o1 = make_float2(d[2] + bv.x, d[3] + bv.y);
            *(float2*)&C[(size_t)(row + mt * 16) * N + col0 + nt * 8] = o0;
            *(float2*)&C[(size_t)(row + mt * 16 + 8) * N + col0 + nt * 8] = o1;
        }
    }
}

// ---------------------------------------------------------------------------
// Fused sparse attention, v2: shuffle-free AV via banded P@V GEMM in smem.
// Keys: rows 0..127 = 128 global (stride-16) keys; rows 128..206 = local
// window strip (t0-15 .. t0+63). P stored transposed [key][query] over the
// dead K tiles after the score phase.
// ---------------------------------------------------------------------------
#define PAD 68
#define TQ 64
#define NKEY 207
#define SMEM_FLOATS ((64 + 208 + 208) * PAD)

__global__ __launch_bounds__(256, 1)
void attn_kernel(const float* __restrict__ qkv, float* __restrict__ out)
{
    const int t0 = blockIdx.x * TQ;
    const int h  = blockIdx.y;
    const int b  = blockIdx.z;
    const int tid = threadIdx.x;

    extern __shared__ float smemf[];
    float* sQ = smemf;                   // [64][PAD]
    float* sV = sQ + 64 * PAD;           // [208][PAD]: 0..127 Vg, 128..206 Vl
    float* sP = sV + 208 * PAD;          // [208][PAD]: K tiles, then P^T

    const size_t baseBT = (size_t)b * TT;
    const int hoff = h * HD;

    // ---- stage ----
    for (int idx = tid; idx < 64 * 16; idx += 256) {
        const int r = idx >> 4, c4 = (idx & 15) * 4;
        *(float4*)&sQ[r * PAD + c4] =
            *(const float4*)&qkv[(baseBT + t0 + r) * D3 + hoff + c4];
    }
    for (int idx = tid; idx < 128 * 16; idx += 256) {
        const int r = idx >> 4, c4 = (idx & 15) * 4;
        const size_t ro = (baseBT + r * 16) * D3 + hoff + c4;
        *(float4*)&sP[r * PAD + c4] = *(const float4*)&qkv[ro + 1024];
        *(float4*)&sV[r * PAD + c4] = *(const float4*)&qkv[ro + 2048];
    }
    for (int idx = tid; idx < 80 * 16; idx += 256) {
        const int r = idx >> 4, c4 = (idx & 15) * 4;
        const int t = t0 - 15 + r;
        float4 kv = make_float4(0.f, 0.f, 0.f, 0.f);
        float4 vv = kv;
        if (r < 79 && t >= 0) {
            const size_t ro = (baseBT + t) * D3 + hoff + c4;
            kv = *(const float4*)&qkv[ro + 1024];
            vv = *(const float4*)&qkv[ro + 2048];
        }
        *(float4*)&sP[(128 + r) * PAD + c4] = kv;
        *(float4*)&sV[(128 + r) * PAD + c4] = vv;
    }
    __syncthreads();

    const int warp = tid >> 5;
    const int lane = tid & 31;
    const float scale = 0.125f;

    // ---- phase 1: scores + softmax, probabilities held in registers ----
    float pg[8][4];
    float pl8[8];
    #pragma unroll
    for (int i = 0; i < 8; ++i) {
        const int qi = warp * 8 + i;
        const float* qrow = &sQ[qi * PAD];

        float sg[4] = {0.f, 0.f, 0.f, 0.f};
        float sl = 0.f;
        const int lrow = 128 + qi + (lane & 15);
        #pragma unroll
        for (int d4 = 0; d4 < 16; ++d4) {
            const float4 qv = *(const float4*)&qrow[d4 * 4];
            #pragma unroll
            for (int c = 0; c < 4; ++c) {
                const float4 kv = *(const float4*)&sP[(lane + c * 32) * PAD + d4 * 4];
                sg[c] += qv.x * kv.x + qv.y * kv.y + qv.z * kv.z + qv.w * kv.w;
            }
            const float4 kl = *(const float4*)&sP[lrow * PAD + d4 * 4];
            sl += qv.x * kl.x + qv.y * kl.y + qv.z * kl.z + qv.w * kl.w;
        }
        sl *= scale;
        #pragma unroll
        for (int c = 0; c < 4; ++c) sg[c] *= scale;

        // local softmax over 16 window slots
        float ml = sl;
        #pragma unroll
        for (int o = 8; o >= 1; o >>= 1)
            ml = fmaxf(ml, __shfl_xor_sync(0xffffffffu, ml, o, 16));
        const float el = __expf(sl - ml);
        float suml = el;
        #pragma unroll
        for (int o = 8; o >= 1; o >>= 1)
            suml += __shfl_xor_sync(0xffffffffu, suml, o, 16);
        pl8[i] = el / suml;

        // global softmax over 128 keys
        float mg = fmaxf(fmaxf(sg[0], sg[1]), fmaxf(sg[2], sg[3]));
        #pragma unroll
        for (int o = 16; o >= 1; o >>= 1)
            mg = fmaxf(mg, __shfl_xor_sync(0xffffffffu, mg, o));
        float eg[4], sumg = 0.f;
        #pragma unroll
        for (int c = 0; c < 4; ++c) { eg[c] = __expf(sg[c] - mg); sumg += eg[c]; }
        #pragma unroll
        for (int o = 16; o >= 1; o >>= 1)
            sumg += __shfl_xor_sync(0xffffffffu, sumg, o);
        const float inv_sumg = 1.f / sumg;
        #pragma unroll
        for (int c = 0; c < 4; ++c) pg[i][c] = eg[c] * inv_sumg;
    }
    __syncthreads();   // K reads done; sP may be overwritten

    // ---- zero the local band region of P^T ----
    const float4 z4 = make_float4(0.f, 0.f, 0.f, 0.f);
    for (int idx = tid; idx < 80 * 16; idx += 256) {
        const int r = idx >> 4, c4 = (idx & 15) * 4;
        *(float4*)&sP[(128 + r) * PAD + c4] = z4;
    }
    __syncthreads();

    // ---- scatter probabilities into P^T [key][query] ----
    #pragma unroll
    for (int i = 0; i < 8; ++i) {
        const int qi = warp * 8 + i;
        #pragma unroll
        for (int c = 0; c < 4; ++c)
            sP[(lane + c * 32) * PAD + qi] = pg[i][c];
        if (lane < 16)
            sP[(128 + qi + lane) * PAD + qi] = pl8[i];
    }
    __syncthreads();

    // ---- phase 2: out[64x64] = P[64x207] @ V[207x64], 4x4 per thread ----
    const int qi0 = (tid & 15) * 4;
    const int d0  = (tid >> 4) * 4;
    float a2[4][4];
    #pragma unroll
    for (int i = 0; i < 4; ++i)
        #pragma unroll
        for (int k = 0; k < 4; ++k) a2[i][k] = 0.f;

    #pragma unroll 3
    for (int j = 0; j < NKEY; ++j) {
        const float4 pv = *(const float4*)&sP[j * PAD + qi0];
        const float4 vv = *(const float4*)&sV[j * PAD + d0];
        a2[0][0] += pv.x * vv.x; a2[0][1] += pv.x * vv.y;
        a2[0][2] += pv.x * vv.z; a2[0][3] += pv.x * vv.w;
        a2[1][0] += pv.y * vv.x; a2[1][1] += pv.y * vv.y;
        a2[1][2] += pv.y * vv.z; a2[1][3] += pv.y * vv.w;
        a2[2][0] += pv.z * vv.x; a2[2][1] += pv.z * vv.y;
        a2[2][2] += pv.z * vv.z; a2[2][3] += pv.z * vv.w;
        a2[3][0] += pv.w * vv.x; a2[3][1] += pv.w * vv.y;
        a2[3][2] += pv.w * vv.z; a2[3][3] += pv.w * vv.w;
    }

    #pragma unroll
    for (int i = 0; i < 4; ++i) {
        const int t = t0 + qi0 + i;
        float4 o;
        o.x = a2[i][0]; o.y = a2[i][1]; o.z = a2[i][2]; o.w = a2[i][3];
        *(float4*)&out[(baseBT + t) * DD + hoff + d0] = o;
    }
}

// ---------------------------------------------------------------------------
extern "C" void kernel_launch(void* const* d_in, const int* in_sizes, int n_in,
                              void* d_out, int out_size)
{
    const float* x      = (const float*)d_in[0];
    const float* w_qkv  = (const float*)d_in[1];
    const float* w_proj = (const float*)d_in[2];
    const float* b_proj = (const float*)d_in[3];
    float* out = (float*)d_out;

    float *qkv, *attn;
    cudaGetSymbolAddress((void**)&qkv,  g_qkv);
    cudaGetSymbolAddress((void**)&attn, g_attn);

    const int M = BB * TT;  // 4096

    cudaFuncSetAttribute(gemm_bf16x3, cudaFuncAttributeMaxDynamicSharedMemorySize, GEMM_SMEM);
    const size_t attn_smem = SMEM_FLOATS * sizeof(float);
    cudaFuncSetAttribute(attn_kernel, cudaFuncAttributeMaxDynamicSharedMemorySize, (int)attn_smem);

    // 1) qkv = x @ w_qkv
    gemm_bf16x3<<<dim3(D3 / 128, M / 128), 256, GEMM_SMEM>>>(x, w_qkv, qkv, M, D3, DD, nullptr);

    // 2) fused sparse attention
    attn_kernel<<<dim3(TT / TQ, HH, BB), 256, attn_smem>>>(qkv, attn);

    // 3) out = attn @ w_proj + b_proj
    gemm_bf16x3<<<dim3(DD / 128, M / 128), 256, GEMM_SMEM>>>(attn, w_proj, out, M, DD, DD, b_proj);
}

// round 5
// speedup vs baseline: 2.4391x; 1.0506x over previous
#include <cuda_runtime.h>
#include <cuda_bf16.h>
#include <cstdint>
#include <cstddef>

// Problem constants
#define BB 2
#define TT 2048
#define DD 1024
#define HH 16
#define HD 64
#define D3 3072

// Scratch (allocation-free rule: __device__ globals)
__device__ float g_qkv[(size_t)BB * TT * D3];
__device__ __nv_bfloat16 g_xh[(size_t)BB * TT * DD];
__device__ __nv_bfloat16 g_xl[(size_t)BB * TT * DD];
__device__ __nv_bfloat16 g_wqh[(size_t)DD * D3];
__device__ __nv_bfloat16 g_wql[(size_t)DD * D3];
__device__ __nv_bfloat16 g_wph[(size_t)DD * DD];
__device__ __nv_bfloat16 g_wpl[(size_t)DD * DD];
__device__ __nv_bfloat16 g_ath[(size_t)BB * TT * DD];
__device__ __nv_bfloat16 g_atl[(size_t)BB * TT * DD];

// ---------------------------------------------------------------------------
// helpers
// ---------------------------------------------------------------------------
__device__ __forceinline__ uint32_t smem_u32(const void* p) {
    uint32_t a;
    asm("{ .reg .u64 t; cvta.to.shared.u64 t, %1; cvt.u32.u64 %0, t; }"
        : "=r"(a) : "l"(p));
    return a;
}
__device__ __forceinline__ void ldsm_x4(uint32_t* r, uint32_t addr) {
    asm volatile("ldmatrix.sync.aligned.m8n8.x4.shared.b16 {%0,%1,%2,%3}, [%4];"
                 : "=r"(r[0]), "=r"(r[1]), "=r"(r[2]), "=r"(r[3]) : "r"(addr));
}
__device__ __forceinline__ void ldsm_x4_t(uint32_t* r, uint32_t addr) {
    asm volatile("ldmatrix.sync.aligned.m8n8.x4.trans.shared.b16 {%0,%1,%2,%3}, [%4];"
                 : "=r"(r[0]), "=r"(r[1]), "=r"(r[2]), "=r"(r[3]) : "r"(addr));
}
__device__ __forceinline__ void mma_bf16(float* d, const uint32_t* a, const uint32_t* b) {
    asm volatile("mma.sync.aligned.m16n8k16.row.col.f32.bf16.bf16.f32 "
                 "{%0,%1,%2,%3}, {%4,%5,%6,%7}, {%8,%9}, {%0,%1,%2,%3};"
                 : "+f"(d[0]), "+f"(d[1]), "+f"(d[2]), "+f"(d[3])
                 : "r"(a[0]), "r"(a[1]), "r"(a[2]), "r"(a[3]),
                   "r"(b[0]), "r"(b[1]));
}
__device__ __forceinline__ void cp16(uint32_t smem_dst, const void* gsrc) {
    asm volatile("cp.async.cg.shared.global [%0], [%1], 16;"
                 :: "r"(smem_dst), "l"(gsrc));
}
__device__ __forceinline__ void cp_commit() {
    asm volatile("cp.async.commit_group;" ::: "memory");
}
template <int N>
__device__ __forceinline__ void cp_wait() {
    asm volatile("cp.async.wait_group %0;" :: "n"(N) : "memory");
}
__device__ __forceinline__ void cvt8(const float4 v, uint2& hi, uint2& lo) {
    __nv_bfloat162 h0 = __floats2bfloat162_rn(v.x, v.y);
    __nv_bfloat162 h1 = __floats2bfloat162_rn(v.z, v.w);
    __nv_bfloat162 l0 = __floats2bfloat162_rn(v.x - __bfloat162float(h0.x),
                                              v.y - __bfloat162float(h0.y));
    __nv_bfloat162 l1 = __floats2bfloat162_rn(v.z - __bfloat162float(h1.x),
                                              v.w - __bfloat162float(h1.y));
    hi.x = *(uint32_t*)&h0; hi.y = *(uint32_t*)&h1;
    lo.x = *(uint32_t*)&l0; lo.y = *(uint32_t*)&l1;
}

// ---------------------------------------------------------------------------
// fp32 -> (bf16 hi, bf16 lo) conversion, vectorized
// ---------------------------------------------------------------------------
__global__ __launch_bounds__(256)
void cvt_hilo(const float* __restrict__ in, __nv_bfloat16* __restrict__ hi,
              __nv_bfloat16* __restrict__ lo, int n4)
{
    const int stride = gridDim.x * blockDim.x;
    for (int i = blockIdx.x * blockDim.x + threadIdx.x; i < n4; i += stride) {
        const float4 v = ((const float4*)in)[i];
        uint2 h, l;
        cvt8(v, h, l);
        ((uint2*)hi)[i] = h;
        ((uint2*)lo)[i] = l;
    }
}

// ---------------------------------------------------------------------------
// bf16-split GEMM v2: C[M,N] = A@W (+bias), operands pre-split bf16 hi/lo.
// CTA tile 128x256, 8 warps (2x4) of 64x64, K-chunk 32, 3-stage cp.async ring.
// C ≈ Ah·Wh + Ah·Wl + Al·Wh
// ---------------------------------------------------------------------------
#define A_STRIDE 40                           // bf16/row (32 + 8 pad)
#define B_STRIDE 264                          // bf16/row (256 + 8 pad)
#define A_BYTES  (128 * A_STRIDE * 2)         // 10240
#define B_BYTES  (32 * B_STRIDE * 2)          // 16896
#define OFF_AL   A_BYTES
#define OFF_BH   (2 * A_BYTES)
#define OFF_BL   (2 * A_BYTES + B_BYTES)
#define STAGE_BYTES (2 * A_BYTES + 2 * B_BYTES)   // 54272
#define NSTAGE 3
#define GEMM_SMEM (NSTAGE * STAGE_BYTES)          // 162816

__global__ __launch_bounds__(256, 1)
void gemm_bf16x3(const __nv_bfloat16* __restrict__ Ah, const __nv_bfloat16* __restrict__ Al,
                 const __nv_bfloat16* __restrict__ Bh, const __nv_bfloat16* __restrict__ Bl,
                 float* __restrict__ C, int M, int N, int K,
                 const float* __restrict__ bias)
{
    extern __shared__ char sm[];
    const uint32_t sb = smem_u32(sm);
    const int tid = threadIdx.x;
    const int lane = tid & 31, wid = tid >> 5;
    const int wm = wid & 1, wn = wid >> 1;          // 2 (m) x 4 (n)
    const int m0 = blockIdx.y * 128, n0 = blockIdx.x * 256;
    const int NC = K >> 5;

    // per-thread cp.async roles
    const int arow = tid >> 2, aseg = tid & 3;       // A: rows arow, arow+64
    const int brow = tid >> 5, bseg = tid & 31;      // B: rows brow+8i

    const __nv_bfloat16* gAh = Ah + (size_t)(m0 + arow) * K + aseg * 8;
    const __nv_bfloat16* gAl = Al + (size_t)(m0 + arow) * K + aseg * 8;
    const __nv_bfloat16* gBh = Bh + (size_t)brow * N + n0 + bseg * 8;
    const __nv_bfloat16* gBl = Bl + (size_t)brow * N + n0 + bseg * 8;
    const uint32_t dA = arow * (A_STRIDE * 2) + aseg * 16;
    const uint32_t dB = brow * (B_STRIDE * 2) + bseg * 16;

    float acc[4][8][4];
    #pragma unroll
    for (int mt = 0; mt < 4; ++mt)
        #pragma unroll
        for (int nt = 0; nt < 8; ++nt)
            #pragma unroll
            for (int q = 0; q < 4; ++q) acc[mt][nt][q] = 0.f;

    // issue one chunk's loads into stage st
    auto issue = [&](int cc, int st) {
        const uint32_t stb = sb + (uint32_t)st * STAGE_BYTES;
        const size_t ka = (size_t)cc * 32;
        #pragma unroll
        for (int i = 0; i < 2; ++i) {
            cp16(stb + dA + i * 64 * (A_STRIDE * 2),        gAh + ka + (size_t)i * 64 * K);
            cp16(stb + OFF_AL + dA + i * 64 * (A_STRIDE * 2), gAl + ka + (size_t)i * 64 * K);
        }
        const size_t kb = (size_t)cc * 32 * N;
        #pragma unroll
        for (int i = 0; i < 4; ++i) {
            cp16(stb + OFF_BH + dB + i * 8 * (B_STRIDE * 2), gBh + kb + (size_t)i * 8 * N);
            cp16(stb + OFF_BL + dB + i * 8 * (B_STRIDE * 2), gBl + kb + (size_t)i * 8 * N);
        }
        cp_commit();
    };

    issue(0, 0);
    if (NC > 1) issue(1, 1);

    // per-warp ldmatrix bases (byte offsets within a stage)
    const uint32_t aRow = ((wm * 64 + (lane & 15)) * A_STRIDE + (lane >> 4) * 8) * 2;
    const int km = (lane & 7) + ((lane >> 3) & 1) * 8;
    const uint32_t bCol = OFF_BH + (km * B_STRIDE + wn * 64 + (lane >> 4) * 8) * 2;

    for (int c = 0; c < NC; ++c) {
        if (c + 2 < NC) { issue(c + 2, (c + 2) % NSTAGE); cp_wait<2>(); }
        else if (c + 1 < NC) cp_wait<1>();
        else cp_wait<0>();
        __syncthreads();

        const uint32_t stb = sb + (uint32_t)(c % NSTAGE) * STAGE_BYTES;
        #pragma unroll
        for (int ks = 0; ks < 2; ++ks) {
            const int k0 = ks * 16;
            uint32_t ahr[4][4], alr[4][4];
            #pragma unroll
            for (int mt = 0; mt < 4; ++mt) {
                ldsm_x4(ahr[mt], stb + aRow + (mt * 16 * A_STRIDE + k0) * 2);
                ldsm_x4(alr[mt], stb + OFF_AL + aRow + (mt * 16 * A_STRIDE + k0) * 2);
            }
            uint32_t bh[16], bl[16];
            #pragma unroll
            for (int j = 0; j < 4; ++j) {
                ldsm_x4_t(bh + j * 4, stb + bCol + (k0 * B_STRIDE + j * 16) * 2);
                ldsm_x4_t(bl + j * 4, stb + B_BYTES + bCol + (k0 * B_STRIDE + j * 16) * 2);
            }
            #pragma unroll
            for (int mt = 0; mt < 4; ++mt)
                #pragma unroll
                for (int nt = 0; nt < 8; ++nt) {
                    mma_bf16(acc[mt][nt], ahr[mt], bh + nt * 2);
                    mma_bf16(acc[mt][nt], ahr[mt], bl + nt * 2);
                    mma_bf16(acc[mt][nt], alr[mt], bh + nt * 2);
                }
        }
        __syncthreads();
    }

    // epilogue
    const int row = m0 + wm * 64 + (lane >> 2);
    const int colb = n0 + wn * 64 + (lane & 3) * 2;
    #pragma unroll
    for (int nt = 0; nt < 8; ++nt) {
        float2 bv = make_float2(0.f, 0.f);
        if (bias) bv = *(const float2*)(bias + colb + nt * 8);
        #pragma unroll
        for (int mt = 0; mt < 4; ++mt) {
            const float* d = acc[mt][nt];
            float2 o0 = make_float2(d[0] + bv.x, d[1] + bv.y);
            float2 o1 = make_float2(d[2] + bv.x, d[3] + bv.y);
            *(float2*)&C[(size_t)(row + mt * 16) * N + colb + nt * 8] = o0;
            *(float2*)&C[(size_t)(row + mt * 16 + 8) * N + colb + nt * 8] = o1;
        }
    }
}

// ---------------------------------------------------------------------------
// Fused sparse attention (R4 version), output emitted as bf16 hi/lo.
// ---------------------------------------------------------------------------
#define PAD 68
#define TQ 64
#define NKEY 207
#define SMEM_FLOATS ((64 + 208 + 208) * PAD)

__global__ __launch_bounds__(256, 1)
void attn_kernel(const float* __restrict__ qkv,
                 __nv_bfloat16* __restrict__ oh, __nv_bfloat16* __restrict__ ol)
{
    const int t0 = blockIdx.x * TQ;
    const int h  = blockIdx.y;
    const int b  = blockIdx.z;
    const int tid = threadIdx.x;

    extern __shared__ float smemf[];
    float* sQ = smemf;
    float* sV = sQ + 64 * PAD;
    float* sP = sV + 208 * PAD;

    const size_t baseBT = (size_t)b * TT;
    const int hoff = h * HD;

    for (int idx = tid; idx < 64 * 16; idx += 256) {
        const int r = idx >> 4, c4 = (idx & 15) * 4;
        *(float4*)&sQ[r * PAD + c4] =
            *(const float4*)&qkv[(baseBT + t0 + r) * D3 + hoff + c4];
    }
    for (int idx = tid; idx < 128 * 16; idx += 256) {
        const int r = idx >> 4, c4 = (idx & 15) * 4;
        const size_t ro = (baseBT + r * 16) * D3 + hoff + c4;
        *(float4*)&sP[r * PAD + c4] = *(const float4*)&qkv[ro + 1024];
        *(float4*)&sV[r * PAD + c4] = *(const float4*)&qkv[ro + 2048];
    }
    for (int idx = tid; idx < 80 * 16; idx += 256) {
        const int r = idx >> 4, c4 = (idx & 15) * 4;
        const int t = t0 - 15 + r;
        float4 kv = make_float4(0.f, 0.f, 0.f, 0.f);
        float4 vv = kv;
        if (r < 79 && t >= 0) {
            const size_t ro = (baseBT + t) * D3 + hoff + c4;
            kv = *(const float4*)&qkv[ro + 1024];
            vv = *(const float4*)&qkv[ro + 2048];
        }
        *(float4*)&sP[(128 + r) * PAD + c4] = kv;
        *(float4*)&sV[(128 + r) * PAD + c4] = vv;
    }
    __syncthreads();

    const int warp = tid >> 5;
    const int lane = tid & 31;
    const float scale = 0.125f;

    float pg[8][4];
    float pl8[8];
    #pragma unroll
    for (int i = 0; i < 8; ++i) {
        const int qi = warp * 8 + i;
        const float* qrow = &sQ[qi * PAD];

        float sg[4] = {0.f, 0.f, 0.f, 0.f};
        float sl = 0.f;
        const int lrow = 128 + qi + (lane & 15);
        #pragma unroll
        for (int d4 = 0; d4 < 16; ++d4) {
            const float4 qv = *(const float4*)&qrow[d4 * 4];
            #pragma unroll
            for (int c = 0; c < 4; ++c) {
                const float4 kv = *(const float4*)&sP[(lane + c * 32) * PAD + d4 * 4];
                sg[c] += qv.x * kv.x + qv.y * kv.y + qv.z * kv.z + qv.w * kv.w;
            }
            const float4 kl = *(const float4*)&sP[lrow * PAD + d4 * 4];
            sl += qv.x * kl.x + qv.y * kl.y + qv.z * kl.z + qv.w * kl.w;
        }
        sl *= scale;
        #pragma unroll
        for (int c = 0; c < 4; ++c) sg[c] *= scale;

        float ml = sl;
        #pragma unroll
        for (int o = 8; o >= 1; o >>= 1)
            ml = fmaxf(ml, __shfl_xor_sync(0xffffffffu, ml, o, 16));
        const float el = __expf(sl - ml);
        float suml = el;
        #pragma unroll
        for (int o = 8; o >= 1; o >>= 1)
            suml += __shfl_xor_sync(0xffffffffu, suml, o, 16);
        pl8[i] = el / suml;

        float mg = fmaxf(fmaxf(sg[0], sg[1]), fmaxf(sg[2], sg[3]));
        #pragma unroll
        for (int o = 16; o >= 1; o >>= 1)
            mg = fmaxf(mg, __shfl_xor_sync(0xffffffffu, mg, o));
        float eg[4], sumg = 0.f;
        #pragma unroll
        for (int c = 0; c < 4; ++c) { eg[c] = __expf(sg[c] - mg); sumg += eg[c]; }
        #pragma unroll
        for (int o = 16; o >= 1; o >>= 1)
            sumg += __shfl_xor_sync(0xffffffffu, sumg, o);
        const float inv_sumg = 1.f / sumg;
        #pragma unroll
        for (int c = 0; c < 4; ++c) pg[i][c] = eg[c] * inv_sumg;
    }
    __syncthreads();

    const float4 z4 = make_float4(0.f, 0.f, 0.f, 0.f);
    for (int idx = tid; idx < 80 * 16; idx += 256) {
        const int r = idx >> 4, c4 = (idx & 15) * 4;
        *(float4*)&sP[(128 + r) * PAD + c4] = z4;
    }
    __syncthreads();

    #pragma unroll
    for (int i = 0; i < 8; ++i) {
        const int qi = warp * 8 + i;
        #pragma unroll
        for (int c = 0; c < 4; ++c)
            sP[(lane + c * 32) * PAD + qi] = pg[i][c];
        if (lane < 16)
            sP[(128 + qi + lane) * PAD + qi] = pl8[i];
    }
    __syncthreads();

    const int qi0 = (tid & 15) * 4;
    const int d0  = (tid >> 4) * 4;
    float a2[4][4];
    #pragma unroll
    for (int i = 0; i < 4; ++i)
        #pragma unroll
        for (int k = 0; k < 4; ++k) a2[i][k] = 0.f;

    #pragma unroll 3
    for (int j = 0; j < NKEY; ++j) {
        const float4 pv = *(const float4*)&sP[j * PAD + qi0];
        const float4 vv = *(const float4*)&sV[j * PAD + d0];
        a2[0][0] += pv.x * vv.x; a2[0][1] += pv.x * vv.y;
        a2[0][2] += pv.x * vv.z; a2[0][3] += pv.x * vv.w;
        a2[1][0] += pv.y * vv.x; a2[1][1] += pv.y * vv.y;
        a2[1][2] += pv.y * vv.z; a2[1][3] += pv.y * vv.w;
        a2[2][0] += pv.z * vv.x; a2[2][1] += pv.z * vv.y;
        a2[2][2] += pv.z * vv.z; a2[2][3] += pv.z * vv.w;
        a2[3][0] += pv.w * vv.x; a2[3][1] += pv.w * vv.y;
        a2[3][2] += pv.w * vv.z; a2[3][3] += pv.w * vv.w;
    }

    #pragma unroll
    for (int i = 0; i < 4; ++i) {
        const int t = t0 + qi0 + i;
        float4 o;
        o.x = a2[i][0]; o.y = a2[i][1]; o.z = a2[i][2]; o.w = a2[i][3];
        uint2 hi, lo;
        cvt8(o, hi, lo);
        const size_t off = (baseBT + t) * DD + hoff + d0;
        *(uint2*)&oh[off] = hi;
        *(uint2*)&ol[off] = lo;
    }
}

// ---------------------------------------------------------------------------
extern "C" void kernel_launch(void* const* d_in, const int* in_sizes, int n_in,
                              void* d_out, int out_size)
{
    const float* x      = (const float*)d_in[0];
    const float* w_qkv  = (const float*)d_in[1];
    const float* w_proj = (const float*)d_in[2];
    const float* b_proj = (const float*)d_in[3];
    float* out = (float*)d_out;

    float* qkv;
    __nv_bfloat16 *xh, *xl, *wqh, *wql, *wph, *wpl, *ath, *atl;
    cudaGetSymbolAddress((void**)&qkv, g_qkv);
    cudaGetSymbolAddress((void**)&xh,  g_xh);
    cudaGetSymbolAddress((void**)&xl,  g_xl);
    cudaGetSymbolAddress((void**)&wqh, g_wqh);
    cudaGetSymbolAddress((void**)&wql, g_wql);
    cudaGetSymbolAddress((void**)&wph, g_wph);
    cudaGetSymbolAddress((void**)&wpl, g_wpl);
    cudaGetSymbolAddress((void**)&ath, g_ath);
    cudaGetSymbolAddress((void**)&atl, g_atl);

    const int M = BB * TT;  // 4096

    cudaFuncSetAttribute(gemm_bf16x3, cudaFuncAttributeMaxDynamicSharedMemorySize, GEMM_SMEM);
    const size_t attn_smem = SMEM_FLOATS * sizeof(float);
    cudaFuncSetAttribute(attn_kernel, cudaFuncAttributeMaxDynamicSharedMemorySize, (int)attn_smem);

    // 0) split inputs/weights into bf16 hi/lo
    cvt_hilo<<<512, 256>>>(x,      xh,  xl,  M * DD / 4);
    cvt_hilo<<<512, 256>>>(w_qkv,  wqh, wql, DD * D3 / 4);
    cvt_hilo<<<512, 256>>>(w_proj, wph, wpl, DD * DD / 4);

    // 1) qkv = x @ w_qkv
    gemm_bf16x3<<<dim3(D3 / 256, M / 128), 256, GEMM_SMEM>>>(
        xh, xl, wqh, wql, qkv, M, D3, DD, nullptr);

    // 2) fused sparse attention (emits bf16 hi/lo)
    attn_kernel<<<dim3(TT / TQ, HH, BB), 256, attn_smem>>>(qkv, ath, atl);

    // 3) out = attn @ w_proj + b_proj
    gemm_bf16x3<<<dim3(DD / 256, M / 128), 256, GEMM_SMEM>>>(
        ath, atl, wph, wpl, out, M, DD, DD, b_proj);
}

// round 7
// speedup vs baseline: 2.4646x; 1.0105x over previous
#include <cuda_runtime.h>
#include <cuda_bf16.h>
#include <cstdint>
#include <cstddef>

// Problem constants
#define BB 2
#define TT 2048
#define DD 1024
#define HH 16
#define HD 64
#define D3 3072

// Scratch (allocation-free rule: __device__ globals)
__device__ float g_qkv[(size_t)BB * TT * D3];
__device__ __nv_bfloat16 g_xh[(size_t)BB * TT * DD];
__device__ __nv_bfloat16 g_xl[(size_t)BB * TT * DD];
__device__ __nv_bfloat16 g_wqh[(size_t)DD * D3];
__device__ __nv_bfloat16 g_wql[(size_t)DD * D3];
__device__ __nv_bfloat16 g_wph[(size_t)DD * DD];
__device__ __nv_bfloat16 g_wpl[(size_t)DD * DD];
__device__ __nv_bfloat16 g_ath[(size_t)BB * TT * DD];
__device__ __nv_bfloat16 g_atl[(size_t)BB * TT * DD];

// ---------------------------------------------------------------------------
// helpers
// ---------------------------------------------------------------------------
__device__ __forceinline__ uint32_t smem_u32(const void* p) {
    uint32_t a;
    asm("{ .reg .u64 t; cvta.to.shared.u64 t, %1; cvt.u32.u64 %0, t; }"
        : "=r"(a) : "l"(p));
    return a;
}
__device__ __forceinline__ void ldsm_x4(uint32_t* r, uint32_t addr) {
    asm volatile("ldmatrix.sync.aligned.m8n8.x4.shared.b16 {%0,%1,%2,%3}, [%4];"
                 : "=r"(r[0]), "=r"(r[1]), "=r"(r[2]), "=r"(r[3]) : "r"(addr));
}
__device__ __forceinline__ void ldsm_x4_t(uint32_t* r, uint32_t addr) {
    asm volatile("ldmatrix.sync.aligned.m8n8.x4.trans.shared.b16 {%0,%1,%2,%3}, [%4];"
                 : "=r"(r[0]), "=r"(r[1]), "=r"(r[2]), "=r"(r[3]) : "r"(addr));
}
__device__ __forceinline__ void mma_bf16(float* d, const uint32_t* a, const uint32_t* b) {
    asm volatile("mma.sync.aligned.m16n8k16.row.col.f32.bf16.bf16.f32 "
                 "{%0,%1,%2,%3}, {%4,%5,%6,%7}, {%8,%9}, {%0,%1,%2,%3};"
                 : "+f"(d[0]), "+f"(d[1]), "+f"(d[2]), "+f"(d[3])
                 : "r"(a[0]), "r"(a[1]), "r"(a[2]), "r"(a[3]),
                   "r"(b[0]), "r"(b[1]));
}
__device__ __forceinline__ void cp16(uint32_t smem_dst, const void* gsrc) {
    asm volatile("cp.async.cg.shared.global [%0], [%1], 16;"
                 :: "r"(smem_dst), "l"(gsrc));
}
__device__ __forceinline__ void cp_commit() {
    asm volatile("cp.async.commit_group;" ::: "memory");
}
template <int N>
__device__ __forceinline__ void cp_wait() {
    asm volatile("cp.async.wait_group %0;" :: "n"(N) : "memory");
}
__device__ __forceinline__ void cvt8(const float4 v, uint2& hi, uint2& lo) {
    __nv_bfloat162 h0 = __floats2bfloat162_rn(v.x, v.y);
    __nv_bfloat162 h1 = __floats2bfloat162_rn(v.z, v.w);
    __nv_bfloat162 l0 = __floats2bfloat162_rn(v.x - __bfloat162float(h0.x),
                                              v.y - __bfloat162float(h0.y));
    __nv_bfloat162 l1 = __floats2bfloat162_rn(v.z - __bfloat162float(h1.x),
                                              v.w - __bfloat162float(h1.y));
    hi.x = *(uint32_t*)&h0; hi.y = *(uint32_t*)&h1;
    lo.x = *(uint32_t*)&l0; lo.y = *(uint32_t*)&l1;
}

// ---------------------------------------------------------------------------
// fp32 -> (bf16 hi, bf16 lo) conversion
// ---------------------------------------------------------------------------
__global__ __launch_bounds__(256)
void cvt_hilo(const float* __restrict__ in, __nv_bfloat16* __restrict__ hi,
              __nv_bfloat16* __restrict__ lo, int n4)
{
    const int stride = gridDim.x * blockDim.x;
    for (int i = blockIdx.x * blockDim.x + threadIdx.x; i < n4; i += stride) {
        const float4 v = ((const float4*)in)[i];
        uint2 h, l;
        cvt8(v, h, l);
        ((uint2*)hi)[i] = h;
        ((uint2*)lo)[i] = l;
    }
}

// ---------------------------------------------------------------------------
// bf16-split GEMM v3: 128x256 CTA tile, 8 warps of 64x64, K-chunk 32,
// 4-stage cp.async ring, ONE barrier per chunk (wait -> sync -> issue).
// ---------------------------------------------------------------------------
#define A_STRIDE 40
#define B_STRIDE 264
#define A_BYTES  (128 * A_STRIDE * 2)
#define B_BYTES  (32 * B_STRIDE * 2)
#define OFF_AL   A_BYTES
#define OFF_BH   (2 * A_BYTES)
#define OFF_BL   (2 * A_BYTES + B_BYTES)
#define STAGE_BYTES (2 * A_BYTES + 2 * B_BYTES)   // 54272
#define NSTAGE 4
#define GEMM_SMEM (NSTAGE * STAGE_BYTES)          // 217088

__global__ __launch_bounds__(256, 1)
void gemm_bf16x3(const __nv_bfloat16* __restrict__ Ah, const __nv_bfloat16* __restrict__ Al,
                 const __nv_bfloat16* __restrict__ Bh, const __nv_bfloat16* __restrict__ Bl,
                 float* __restrict__ C, int M, int N, int K,
                 const float* __restrict__ bias)
{
    extern __shared__ char sm[];
    const uint32_t sb = smem_u32(sm);
    const int tid = threadIdx.x;
    const int lane = tid & 31, wid = tid >> 5;
    const int wm = wid & 1, wn = wid >> 1;
    const int m0 = blockIdx.y * 128, n0 = blockIdx.x * 256;
    const int NC = K >> 5;

    const int arow = tid >> 2, aseg = tid & 3;
    const int brow = tid >> 5, bseg = tid & 31;

    const __nv_bfloat16* gAh = Ah + (size_t)(m0 + arow) * K + aseg * 8;
    const __nv_bfloat16* gAl = Al + (size_t)(m0 + arow) * K + aseg * 8;
    const __nv_bfloat16* gBh = Bh + (size_t)brow * N + n0 + bseg * 8;
    const __nv_bfloat16* gBl = Bl + (size_t)brow * N + n0 + bseg * 8;
    const uint32_t dA = arow * (A_STRIDE * 2) + aseg * 16;
    const uint32_t dB = brow * (B_STRIDE * 2) + bseg * 16;

    float acc[4][8][4];
    #pragma unroll
    for (int mt = 0; mt < 4; ++mt)
        #pragma unroll
        for (int nt = 0; nt < 8; ++nt)
            #pragma unroll
            for (int q = 0; q < 4; ++q) acc[mt][nt][q] = 0.f;

    auto issue = [&](int cc, int st) {
        const uint32_t stb = sb + (uint32_t)st * STAGE_BYTES;
        const size_t ka = (size_t)cc * 32;
        #pragma unroll
        for (int i = 0; i < 2; ++i) {
            cp16(stb + dA + i * 64 * (A_STRIDE * 2),          gAh + ka + (size_t)i * 64 * K);
            cp16(stb + OFF_AL + dA + i * 64 * (A_STRIDE * 2), gAl + ka + (size_t)i * 64 * K);
        }
        const size_t kb = (size_t)cc * 32 * N;
        #pragma unroll
        for (int i = 0; i < 4; ++i) {
            cp16(stb + OFF_BH + dB + i * 8 * (B_STRIDE * 2), gBh + kb + (size_t)i * 8 * N);
            cp16(stb + OFF_BL + dB + i * 8 * (B_STRIDE * 2), gBl + kb + (size_t)i * 8 * N);
        }
        cp_commit();
    };

    issue(0, 0);
    if (NC > 1) issue(1, 1);
    if (NC > 2) issue(2, 2);

    const uint32_t aRow = ((wm * 64 + (lane & 15)) * A_STRIDE + (lane >> 4) * 8) * 2;
    const int km = (lane & 7) + ((lane >> 3) & 1) * 8;
    const uint32_t bCol = OFF_BH + (km * B_STRIDE + wn * 64 + (lane >> 4) * 8) * 2;

    for (int c = 0; c < NC; ++c) {
        if (c + 2 < NC) cp_wait<2>();
        else if (c + 1 < NC) cp_wait<1>();
        else cp_wait<0>();
        __syncthreads();
        // safe: stage (c+3)&3 == (c-1)&3, whose readers all passed the sync above
        if (c + 3 < NC) issue(c + 3, (c + 3) & 3);

        const uint32_t stb = sb + (uint32_t)(c & 3) * STAGE_BYTES;
        #pragma unroll
        for (int ks = 0; ks < 2; ++ks) {
            const int k0 = ks * 16;
            uint32_t ahr[4][4], alr[4][4];
            #pragma unroll
            for (int mt = 0; mt < 4; ++mt) {
                ldsm_x4(ahr[mt], stb + aRow + (mt * 16 * A_STRIDE + k0) * 2);
                ldsm_x4(alr[mt], stb + OFF_AL + aRow + (mt * 16 * A_STRIDE + k0) * 2);
            }
            uint32_t bh[16], bl[16];
            #pragma unroll
            for (int j = 0; j < 4; ++j) {
                ldsm_x4_t(bh + j * 4, stb + bCol + (k0 * B_STRIDE + j * 16) * 2);
                ldsm_x4_t(bl + j * 4, stb + B_BYTES + bCol + (k0 * B_STRIDE + j * 16) * 2);
            }
            #pragma unroll
            for (int mt = 0; mt < 4; ++mt)
                #pragma unroll
                for (int nt = 0; nt < 8; ++nt) {
                    mma_bf16(acc[mt][nt], ahr[mt], bh + nt * 2);
                    mma_bf16(acc[mt][nt], ahr[mt], bl + nt * 2);
                    mma_bf16(acc[mt][nt], alr[mt], bh + nt * 2);
                }
        }
    }

    const int row = m0 + wm * 64 + (lane >> 2);
    const int colb = n0 + wn * 64 + (lane & 3) * 2;
    #pragma unroll
    for (int nt = 0; nt < 8; ++nt) {
        float2 bv = make_float2(0.f, 0.f);
        if (bias) bv = *(const float2*)(bias + colb + nt * 8);
        #pragma unroll
        for (int mt = 0; mt < 4; ++mt) {
            const float* d = acc[mt][nt];
            float2 o0 = make_float2(d[0] + bv.x, d[1] + bv.y);
            float2 o1 = make_float2(d[2] + bv.x, d[3] + bv.y);
            *(float2*)&C[(size_t)(row + mt * 16) * N + colb + nt * 8] = o0;
            *(float2*)&C[(size_t)(row + mt * 16 + 8) * N + colb + nt * 8] = o1;
        }
    }
}

// ---------------------------------------------------------------------------
// Fused sparse attention (R5 known-good version, TQ=64, 256 threads).
// P^T [key][query] requires query count <= PAD; TQ=64 < 68 OK.
// ---------------------------------------------------------------------------
#define PAD 68
#define TQ 64
#define NKEY 207
#define SMEM_FLOATS ((64 + 208 + 208) * PAD)

__global__ __launch_bounds__(256, 1)
void attn_kernel(const float* __restrict__ qkv,
                 __nv_bfloat16* __restrict__ oh, __nv_bfloat16* __restrict__ ol)
{
    const int t0 = blockIdx.x * TQ;
    const int h  = blockIdx.y;
    const int b  = blockIdx.z;
    const int tid = threadIdx.x;

    extern __shared__ float smemf[];
    float* sQ = smemf;
    float* sV = sQ + 64 * PAD;
    float* sP = sV + 208 * PAD;

    const size_t baseBT = (size_t)b * TT;
    const int hoff = h * HD;

    for (int idx = tid; idx < 64 * 16; idx += 256) {
        const int r = idx >> 4, c4 = (idx & 15) * 4;
        *(float4*)&sQ[r * PAD + c4] =
            *(const float4*)&qkv[(baseBT + t0 + r) * D3 + hoff + c4];
    }
    for (int idx = tid; idx < 128 * 16; idx += 256) {
        const int r = idx >> 4, c4 = (idx & 15) * 4;
        const size_t ro = (baseBT + r * 16) * D3 + hoff + c4;
        *(float4*)&sP[r * PAD + c4] = *(const float4*)&qkv[ro + 1024];
        *(float4*)&sV[r * PAD + c4] = *(const float4*)&qkv[ro + 2048];
    }
    for (int idx = tid; idx < 80 * 16; idx += 256) {
        const int r = idx >> 4, c4 = (idx & 15) * 4;
        const int t = t0 - 15 + r;
        float4 kv = make_float4(0.f, 0.f, 0.f, 0.f);
        float4 vv = kv;
        if (r < 79 && t >= 0) {
            const size_t ro = (baseBT + t) * D3 + hoff + c4;
            kv = *(const float4*)&qkv[ro + 1024];
            vv = *(const float4*)&qkv[ro + 2048];
        }
        *(float4*)&sP[(128 + r) * PAD + c4] = kv;
        *(float4*)&sV[(128 + r) * PAD + c4] = vv;
    }
    __syncthreads();

    const int warp = tid >> 5;
    const int lane = tid & 31;
    const float scale = 0.125f;

    float pg[8][4];
    float pl8[8];
    #pragma unroll
    for (int i = 0; i < 8; ++i) {
        const int qi = warp * 8 + i;
        const float* qrow = &sQ[qi * PAD];

        float sg[4] = {0.f, 0.f, 0.f, 0.f};
        float sl = 0.f;
        const int lrow = 128 + qi + (lane & 15);
        #pragma unroll
        for (int d4 = 0; d4 < 16; ++d4) {
            const float4 qv = *(const float4*)&qrow[d4 * 4];
            #pragma unroll
            for (int c = 0; c < 4; ++c) {
                const float4 kv = *(const float4*)&sP[(lane + c * 32) * PAD + d4 * 4];
                sg[c] += qv.x * kv.x + qv.y * kv.y + qv.z * kv.z + qv.w * kv.w;
            }
            const float4 kl = *(const float4*)&sP[lrow * PAD + d4 * 4];
            sl += qv.x * kl.x + qv.y * kl.y + qv.z * kl.z + qv.w * kl.w;
        }
        sl *= scale;
        #pragma unroll
        for (int c = 0; c < 4; ++c) sg[c] *= scale;

        float ml = sl;
        #pragma unroll
        for (int o = 8; o >= 1; o >>= 1)
            ml = fmaxf(ml, __shfl_xor_sync(0xffffffffu, ml, o, 16));
        const float el = __expf(sl - ml);
        float suml = el;
        #pragma unroll
        for (int o = 8; o >= 1; o >>= 1)
            suml += __shfl_xor_sync(0xffffffffu, suml, o, 16);
        pl8[i] = el / suml;

        float mg = fmaxf(fmaxf(sg[0], sg[1]), fmaxf(sg[2], sg[3]));
        #pragma unroll
        for (int o = 16; o >= 1; o >>= 1)
            mg = fmaxf(mg, __shfl_xor_sync(0xffffffffu, mg, o));
        float eg[4], sumg = 0.f;
        #pragma unroll
        for (int c = 0; c < 4; ++c) { eg[c] = __expf(sg[c] - mg); sumg += eg[c]; }
        #pragma unroll
        for (int o = 16; o >= 1; o >>= 1)
            sumg += __shfl_xor_sync(0xffffffffu, sumg, o);
        const float inv_sumg = 1.f / sumg;
        #pragma unroll
        for (int c = 0; c < 4; ++c) pg[i][c] = eg[c] * inv_sumg;
    }
    __syncthreads();

    const float4 z4 = make_float4(0.f, 0.f, 0.f, 0.f);
    for (int idx = tid; idx < 80 * 16; idx += 256) {
        const int r = idx >> 4, c4 = (idx & 15) * 4;
        *(float4*)&sP[(128 + r) * PAD + c4] = z4;
    }
    __syncthreads();

    #pragma unroll
    for (int i = 0; i < 8; ++i) {
        const int qi = warp * 8 + i;
        #pragma unroll
        for (int c = 0; c < 4; ++c)
            sP[(lane + c * 32) * PAD + qi] = pg[i][c];
        if (lane < 16)
            sP[(128 + qi + lane) * PAD + qi] = pl8[i];
    }
    __syncthreads();

    const int qi0 = (tid & 15) * 4;
    const int d0  = (tid >> 4) * 4;
    float a2[4][4];
    #pragma unroll
    for (int i = 0; i < 4; ++i)
        #pragma unroll
        for (int k = 0; k < 4; ++k) a2[i][k] = 0.f;

    #pragma unroll 3
    for (int j = 0; j < NKEY; ++j) {
        const float4 pv = *(const float4*)&sP[j * PAD + qi0];
        const float4 vv = *(const float4*)&sV[j * PAD + d0];
        a2[0][0] += pv.x * vv.x; a2[0][1] += pv.x * vv.y;
        a2[0][2] += pv.x * vv.z; a2[0][3] += pv.x * vv.w;
        a2[1][0] += pv.y * vv.x; a2[1][1] += pv.y * vv.y;
        a2[1][2] += pv.y * vv.z; a2[1][3] += pv.y * vv.w;
        a2[2][0] += pv.z * vv.x; a2[2][1] += pv.z * vv.y;
        a2[2][2] += pv.z * vv.z; a2[2][3] += pv.z * vv.w;
        a2[3][0] += pv.w * vv.x; a2[3][1] += pv.w * vv.y;
        a2[3][2] += pv.w * vv.z; a2[3][3] += pv.w * vv.w;
    }

    #pragma unroll
    for (int i = 0; i < 4; ++i) {
        const int t = t0 + qi0 + i;
        float4 o;
        o.x = a2[i][0]; o.y = a2[i][1]; o.z = a2[i][2]; o.w = a2[i][3];
        uint2 hi, lo;
        cvt8(o, hi, lo);
        const size_t off = (baseBT + t) * DD + hoff + d0;
        *(uint2*)&oh[off] = hi;
        *(uint2*)&ol[off] = lo;
    }
}

// ---------------------------------------------------------------------------
extern "C" void kernel_launch(void* const* d_in, const int* in_sizes, int n_in,
                              void* d_out, int out_size)
{
    const float* x      = (const float*)d_in[0];
    const float* w_qkv  = (const float*)d_in[1];
    const float* w_proj = (const float*)d_in[2];
    const float* b_proj = (const float*)d_in[3];
    float* out = (float*)d_out;

    float* qkv;
    __nv_bfloat16 *xh, *xl, *wqh, *wql, *wph, *wpl, *ath, *atl;
    cudaGetSymbolAddress((void**)&qkv, g_qkv);
    cudaGetSymbolAddress((void**)&xh,  g_xh);
    cudaGetSymbolAddress((void**)&xl,  g_xl);
    cudaGetSymbolAddress((void**)&wqh, g_wqh);
    cudaGetSymbolAddress((void**)&wql, g_wql);
    cudaGetSymbolAddress((void**)&wph, g_wph);
    cudaGetSymbolAddress((void**)&wpl, g_wpl);
    cudaGetSymbolAddress((void**)&ath, g_ath);
    cudaGetSymbolAddress((void**)&atl, g_atl);

    const int M = BB * TT;  // 4096

    cudaFuncSetAttribute(gemm_bf16x3, cudaFuncAttributeMaxDynamicSharedMemorySize, GEMM_SMEM);
    const size_t attn_smem = SMEM_FLOATS * sizeof(float);
    cudaFuncSetAttribute(attn_kernel, cudaFuncAttributeMaxDynamicSharedMemorySize, (int)attn_smem);

    // 0) split inputs/weights into bf16 hi/lo
    cvt_hilo<<<512, 256>>>(x,      xh,  xl,  M * DD / 4);
    cvt_hilo<<<512, 256>>>(w_qkv,  wqh, wql, DD * D3 / 4);
    cvt_hilo<<<512, 256>>>(w_proj, wph, wpl, DD * DD / 4);

    // 1) qkv = x @ w_qkv
    gemm_bf16x3<<<dim3(D3 / 256, M / 128), 256, GEMM_SMEM>>>(
        xh, xl, wqh, wql, qkv, M, D3, DD, nullptr);

    // 2) fused sparse attention (emits bf16 hi/lo)
    attn_kernel<<<dim3(TT / TQ, HH, BB), 256, attn_smem>>>(qkv, ath, atl);

    // 3) out = attn @ w_proj + b_proj
    gemm_bf16x3<<<dim3(DD / 256, M / 128), 256, GEMM_SMEM>>>(
        ath, atl, wph, wpl, out, M, DD, DD, b_proj);
}

// round 8
// speedup vs baseline: 2.9087x; 1.1802x over previous
#include <cuda_runtime.h>
#include <cuda_bf16.h>
#include <cstdint>
#include <cstddef>

// Problem constants
#define BB 2
#define TT 2048
#define DD 1024
#define HH 16
#define HD 64
#define D3 3072

// Scratch (allocation-free rule: __device__ globals)
__device__ float g_qkv[(size_t)BB * TT * D3];
__device__ __nv_bfloat16 g_xh[(size_t)BB * TT * DD];
__device__ __nv_bfloat16 g_xl[(size_t)BB * TT * DD];
__device__ __nv_bfloat16 g_wqh[(size_t)DD * D3];
__device__ __nv_bfloat16 g_wql[(size_t)DD * D3];
__device__ __nv_bfloat16 g_wph[(size_t)DD * DD];
__device__ __nv_bfloat16 g_wpl[(size_t)DD * DD];
__device__ __nv_bfloat16 g_ath[(size_t)BB * TT * DD];
__device__ __nv_bfloat16 g_atl[(size_t)BB * TT * DD];

// ---------------------------------------------------------------------------
// helpers
// ---------------------------------------------------------------------------
__device__ __forceinline__ uint32_t smem_u32(const void* p) {
    uint32_t a;
    asm("{ .reg .u64 t; cvta.to.shared.u64 t, %1; cvt.u32.u64 %0, t; }"
        : "=r"(a) : "l"(p));
    return a;
}
__device__ __forceinline__ void ldsm_x4(uint32_t* r, uint32_t addr) {
    asm volatile("ldmatrix.sync.aligned.m8n8.x4.shared.b16 {%0,%1,%2,%3}, [%4];"
                 : "=r"(r[0]), "=r"(r[1]), "=r"(r[2]), "=r"(r[3]) : "r"(addr));
}
__device__ __forceinline__ void ldsm_x4_t(uint32_t* r, uint32_t addr) {
    asm volatile("ldmatrix.sync.aligned.m8n8.x4.trans.shared.b16 {%0,%1,%2,%3}, [%4];"
                 : "=r"(r[0]), "=r"(r[1]), "=r"(r[2]), "=r"(r[3]) : "r"(addr));
}
__device__ __forceinline__ void mma_bf16(float* d, const uint32_t* a, const uint32_t* b) {
    asm volatile("mma.sync.aligned.m16n8k16.row.col.f32.bf16.bf16.f32 "
                 "{%0,%1,%2,%3}, {%4,%5,%6,%7}, {%8,%9}, {%0,%1,%2,%3};"
                 : "+f"(d[0]), "+f"(d[1]), "+f"(d[2]), "+f"(d[3])
                 : "r"(a[0]), "r"(a[1]), "r"(a[2]), "r"(a[3]),
                   "r"(b[0]), "r"(b[1]));
}
__device__ __forceinline__ void cp16(uint32_t smem_dst, const void* gsrc) {
    asm volatile("cp.async.cg.shared.global [%0], [%1], 16;"
                 :: "r"(smem_dst), "l"(gsrc));
}
__device__ __forceinline__ void cp_commit() {
    asm volatile("cp.async.commit_group;" ::: "memory");
}
template <int N>
__device__ __forceinline__ void cp_wait() {
    asm volatile("cp.async.wait_group %0;" :: "n"(N) : "memory");
}
__device__ __forceinline__ void cvt8(const float4 v, uint2& hi, uint2& lo) {
    __nv_bfloat162 h0 = __floats2bfloat162_rn(v.x, v.y);
    __nv_bfloat162 h1 = __floats2bfloat162_rn(v.z, v.w);
    __nv_bfloat162 l0 = __floats2bfloat162_rn(v.x - __bfloat162float(h0.x),
                                              v.y - __bfloat162float(h0.y));
    __nv_bfloat162 l1 = __floats2bfloat162_rn(v.z - __bfloat162float(h1.x),
                                              v.w - __bfloat162float(h1.y));
    hi.x = *(uint32_t*)&h0; hi.y = *(uint32_t*)&h1;
    lo.x = *(uint32_t*)&l0; lo.y = *(uint32_t*)&l1;
}
__device__ __forceinline__ uint32_t pack_hi2(float a, float b) {
    __nv_bfloat162 t = __floats2bfloat162_rn(a, b);
    return *(uint32_t*)&t;
}
__device__ __forceinline__ uint32_t pack_lo2(float a, float b, uint32_t hi) {
    __nv_bfloat162 h = *(__nv_bfloat162*)&hi;
    __nv_bfloat162 t = __floats2bfloat162_rn(a - __bfloat162float(h.x),
                                             b - __bfloat162float(h.y));
    return *(uint32_t*)&t;
}

// ---------------------------------------------------------------------------
// fp32 -> (bf16 hi, bf16 lo) conversion
// ---------------------------------------------------------------------------
__global__ __launch_bounds__(256)
void cvt_hilo(const float* __restrict__ in, __nv_bfloat16* __restrict__ hi,
              __nv_bfloat16* __restrict__ lo, int n4)
{
    const int stride = gridDim.x * blockDim.x;
    for (int i = blockIdx.x * blockDim.x + threadIdx.x; i < n4; i += stride) {
        const float4 v = ((const float4*)in)[i];
        uint2 h, l;
        cvt8(v, h, l);
        ((uint2*)hi)[i] = h;
        ((uint2*)lo)[i] = l;
    }
}

// ---------------------------------------------------------------------------
// bf16-split GEMM v3 (unchanged R7 win)
// ---------------------------------------------------------------------------
#define A_STRIDE 40
#define B_STRIDE 264
#define A_BYTES  (128 * A_STRIDE * 2)
#define B_BYTES  (32 * B_STRIDE * 2)
#define OFF_AL   A_BYTES
#define OFF_BH   (2 * A_BYTES)
#define OFF_BL   (2 * A_BYTES + B_BYTES)
#define STAGE_BYTES (2 * A_BYTES + 2 * B_BYTES)
#define NSTAGE 4
#define GEMM_SMEM (NSTAGE * STAGE_BYTES)

__global__ __launch_bounds__(256, 1)
void gemm_bf16x3(const __nv_bfloat16* __restrict__ Ah, const __nv_bfloat16* __restrict__ Al,
                 const __nv_bfloat16* __restrict__ Bh, const __nv_bfloat16* __restrict__ Bl,
                 float* __restrict__ C, int M, int N, int K,
                 const float* __restrict__ bias)
{
    extern __shared__ char sm[];
    const uint32_t sb = smem_u32(sm);
    const int tid = threadIdx.x;
    const int lane = tid & 31, wid = tid >> 5;
    const int wm = wid & 1, wn = wid >> 1;
    const int m0 = blockIdx.y * 128, n0 = blockIdx.x * 256;
    const int NC = K >> 5;

    const int arow = tid >> 2, aseg = tid & 3;
    const int brow = tid >> 5, bseg = tid & 31;

    const __nv_bfloat16* gAh = Ah + (size_t)(m0 + arow) * K + aseg * 8;
    const __nv_bfloat16* gAl = Al + (size_t)(m0 + arow) * K + aseg * 8;
    const __nv_bfloat16* gBh = Bh + (size_t)brow * N + n0 + bseg * 8;
    const __nv_bfloat16* gBl = Bl + (size_t)brow * N + n0 + bseg * 8;
    const uint32_t dA = arow * (A_STRIDE * 2) + aseg * 16;
    const uint32_t dB = brow * (B_STRIDE * 2) + bseg * 16;

    float acc[4][8][4];
    #pragma unroll
    for (int mt = 0; mt < 4; ++mt)
        #pragma unroll
        for (int nt = 0; nt < 8; ++nt)
            #pragma unroll
            for (int q = 0; q < 4; ++q) acc[mt][nt][q] = 0.f;

    auto issue = [&](int cc, int st) {
        const uint32_t stb = sb + (uint32_t)st * STAGE_BYTES;
        const size_t ka = (size_t)cc * 32;
        #pragma unroll
        for (int i = 0; i < 2; ++i) {
            cp16(stb + dA + i * 64 * (A_STRIDE * 2),          gAh + ka + (size_t)i * 64 * K);
            cp16(stb + OFF_AL + dA + i * 64 * (A_STRIDE * 2), gAl + ka + (size_t)i * 64 * K);
        }
        const size_t kb = (size_t)cc * 32 * N;
        #pragma unroll
        for (int i = 0; i < 4; ++i) {
            cp16(stb + OFF_BH + dB + i * 8 * (B_STRIDE * 2), gBh + kb + (size_t)i * 8 * N);
            cp16(stb + OFF_BL + dB + i * 8 * (B_STRIDE * 2), gBl + kb + (size_t)i * 8 * N);
        }
        cp_commit();
    };

    issue(0, 0);
    if (NC > 1) issue(1, 1);
    if (NC > 2) issue(2, 2);

    const uint32_t aRow = ((wm * 64 + (lane & 15)) * A_STRIDE + (lane >> 4) * 8) * 2;
    const int km = (lane & 7) + ((lane >> 3) & 1) * 8;
    const uint32_t bCol = OFF_BH + (km * B_STRIDE + wn * 64 + (lane >> 4) * 8) * 2;

    for (int c = 0; c < NC; ++c) {
        if (c + 2 < NC) cp_wait<2>();
        else if (c + 1 < NC) cp_wait<1>();
        else cp_wait<0>();
        __syncthreads();
        if (c + 3 < NC) issue(c + 3, (c + 3) & 3);

        const uint32_t stb = sb + (uint32_t)(c & 3) * STAGE_BYTES;
        #pragma unroll
        for (int ks = 0; ks < 2; ++ks) {
            const int k0 = ks * 16;
            uint32_t ahr[4][4], alr[4][4];
            #pragma unroll
            for (int mt = 0; mt < 4; ++mt) {
                ldsm_x4(ahr[mt], stb + aRow + (mt * 16 * A_STRIDE + k0) * 2);
                ldsm_x4(alr[mt], stb + OFF_AL + aRow + (mt * 16 * A_STRIDE + k0) * 2);
            }
            uint32_t bh[16], bl[16];
            #pragma unroll
            for (int j = 0; j < 4; ++j) {
                ldsm_x4_t(bh + j * 4, stb + bCol + (k0 * B_STRIDE + j * 16) * 2);
                ldsm_x4_t(bl + j * 4, stb + B_BYTES + bCol + (k0 * B_STRIDE + j * 16) * 2);
            }
            #pragma unroll
            for (int mt = 0; mt < 4; ++mt)
                #pragma unroll
                for (int nt = 0; nt < 8; ++nt) {
                    mma_bf16(acc[mt][nt], ahr[mt], bh + nt * 2);
                    mma_bf16(acc[mt][nt], ahr[mt], bl + nt * 2);
                    mma_bf16(acc[mt][nt], alr[mt], bh + nt * 2);
                }
        }
    }

    const int row = m0 + wm * 64 + (lane >> 2);
    const int colb = n0 + wn * 64 + (lane & 3) * 2;
    #pragma unroll
    for (int nt = 0; nt < 8; ++nt) {
        float2 bv = make_float2(0.f, 0.f);
        if (bias) bv = *(const float2*)(bias + colb + nt * 8);
        #pragma unroll
        for (int mt = 0; mt < 4; ++mt) {
            const float* d = acc[mt][nt];
            float2 o0 = make_float2(d[0] + bv.x, d[1] + bv.y);
            float2 o1 = make_float2(d[2] + bv.x, d[3] + bv.y);
            *(float2*)&C[(size_t)(row + mt * 16) * N + colb + nt * 8] = o0;
            *(float2*)&C[(size_t)(row + mt * 16 + 8) * N + colb + nt * 8] = o1;
        }
    }
}

// ---------------------------------------------------------------------------
// Tensor-core sparse attention. Block = (b, h, 64-query tile), 8 warps.
// Keys padded to 224: n<128 global (t=n*16), 128..206 local strip (t0-15+r),
// 207..223 zero pad. Warp (mtile=w&3, half=w>>2): S rows mtile*16..+15,
// key half [half*112, half*112+112). bf16x3 for QK^T and PV.
// ---------------------------------------------------------------------------
#define KSTR 72
#define SQH 0
#define SQL (64 * KSTR * 2)
#define SKH (2 * 64 * KSTR * 2)                  // 18432
#define SKL (SKH + 224 * KSTR * 2)
#define SVH (SKL + 224 * KSTR * 2)
#define SVL (SVH + 224 * KSTR * 2)
#define SRED (SVL + 224 * KSTR * 2)              // 147456
#define SO  SKH
#define ATTN_SMEM (SRED + 1024)

__global__ __launch_bounds__(256, 1)
void attn_mma(const float* __restrict__ qkv,
              __nv_bfloat16* __restrict__ oh, __nv_bfloat16* __restrict__ ol)
{
    const int t0 = blockIdx.x * 64;
    const int h  = blockIdx.y;
    const int b  = blockIdx.z;
    const int tid = threadIdx.x;
    const int lane = tid & 31, wid = tid >> 5;
    const int mtile = wid & 3, half = wid >> 2;

    extern __shared__ char sm[];
    const uint32_t sb = smem_u32(sm);
    const size_t baseBT = (size_t)b * TT;
    const int hoff = h * HD;

    // ---- stage Q (64 rows) ----
    for (int idx = tid; idx < 64 * 16; idx += 256) {
        const int r = idx >> 4, c4 = (idx & 15) * 4;
        const float4 v = *(const float4*)&qkv[(baseBT + t0 + r) * D3 + hoff + c4];
        uint2 hi, lo; cvt8(v, hi, lo);
        const uint32_t off = (r * KSTR + c4) * 2;
        *(uint2*)(sm + SQH + off) = hi;
        *(uint2*)(sm + SQL + off) = lo;
    }
    // ---- stage K/V (224 rows) ----
    for (int idx = tid; idx < 224 * 16; idx += 256) {
        const int r = idx >> 4, c4 = (idx & 15) * 4;
        int t = 0; bool valid = false;
        if (r < 128)      { t = r * 16;              valid = true; }
        else if (r < 207) { t = t0 - 15 + (r - 128); valid = (t >= 0); }
        float4 kv = make_float4(0.f, 0.f, 0.f, 0.f), vv = kv;
        if (valid) {
            const size_t ro = (baseBT + t) * D3 + hoff + c4;
            kv = *(const float4*)&qkv[ro + 1024];
            vv = *(const float4*)&qkv[ro + 2048];
        }
        uint2 khi, klo, vhi, vlo;
        cvt8(kv, khi, klo); cvt8(vv, vhi, vlo);
        const uint32_t off = (r * KSTR + c4) * 2;
        *(uint2*)(sm + SKH + off) = khi;
        *(uint2*)(sm + SKL + off) = klo;
        *(uint2*)(sm + SVH + off) = vhi;
        *(uint2*)(sm + SVL + off) = vlo;
    }
    __syncthreads();

    // ---- phase 1: S = Q @ K^T (bf16x3) ----
    uint32_t qh[4][4], ql[4][4];
    const uint32_t aQ = sb + SQH + ((mtile * 16 + (lane & 15)) * KSTR + (lane >> 4) * 8) * 2;
    #pragma unroll
    for (int kc = 0; kc < 4; ++kc) {
        ldsm_x4(qh[kc], aQ + kc * 32);
        ldsm_x4(ql[kc], aQ + (SQL - SQH) + kc * 32);
    }

    const uint32_t bK = sb + SKH +
        ((half * 112 + (lane & 7) + ((lane >> 4) & 1) * 8) * KSTR + ((lane >> 3) & 1) * 8) * 2;

    float cf[14][4];
    #pragma unroll
    for (int j = 0; j < 14; ++j)
        #pragma unroll
        for (int e = 0; e < 4; ++e) cf[j][e] = 0.f;

    #pragma unroll
    for (int jj = 0; jj < 7; ++jj) {
        #pragma unroll
        for (int kc = 0; kc < 4; ++kc) {
            uint32_t kh4[4], kl4[4];
            const uint32_t ad = bK + (jj * 16 * KSTR + kc * 16) * 2;
            ldsm_x4(kh4, ad);
            ldsm_x4(kl4, ad + (SKL - SKH));
            mma_bf16(cf[2 * jj],     qh[kc], kh4 + 0);
            mma_bf16(cf[2 * jj],     qh[kc], kl4 + 0);
            mma_bf16(cf[2 * jj],     ql[kc], kh4 + 0);
            mma_bf16(cf[2 * jj + 1], qh[kc], kh4 + 2);
            mma_bf16(cf[2 * jj + 1], qh[kc], kl4 + 2);
            mma_bf16(cf[2 * jj + 1], ql[kc], kh4 + 2);
        }
    }
    #pragma unroll
    for (int j = 0; j < 14; ++j)
        #pragma unroll
        for (int e = 0; e < 4; ++e) cf[j][e] *= 0.125f;

    // ---- softmax ----
    const int r0 = mtile * 16 + (lane >> 2);   // query idx 0..63
    const int r1 = r0 + 8;
    float* sMax = (float*)(sm + SRED);         // [2][64]
    float* sSum = (float*)(sm + SRED + 512);   // [2][64]
    const int jg = (half == 0) ? 14 : 2;       // # global tiles this warp

    float gm0 = -1e30f, gm1 = -1e30f;
    for (int j = 0; j < jg; ++j) {
        gm0 = fmaxf(gm0, fmaxf(cf[j][0], cf[j][1]));
        gm1 = fmaxf(gm1, fmaxf(cf[j][2], cf[j][3]));
    }
    gm0 = fmaxf(gm0, __shfl_xor_sync(0xffffffffu, gm0, 1));
    gm0 = fmaxf(gm0, __shfl_xor_sync(0xffffffffu, gm0, 2));
    gm1 = fmaxf(gm1, __shfl_xor_sync(0xffffffffu, gm1, 1));
    gm1 = fmaxf(gm1, __shfl_xor_sync(0xffffffffu, gm1, 2));
    if ((lane & 3) == 0) { sMax[half * 64 + r0] = gm0; sMax[half * 64 + r1] = gm1; }
    __syncthreads();
    const float M0 = fmaxf(sMax[r0], sMax[64 + r0]);
    const float M1 = fmaxf(sMax[r1], sMax[64 + r1]);

    float gs0 = 0.f, gs1 = 0.f;
    for (int j = 0; j < jg; ++j) {
        cf[j][0] = __expf(cf[j][0] - M0); cf[j][1] = __expf(cf[j][1] - M0);
        cf[j][2] = __expf(cf[j][2] - M1); cf[j][3] = __expf(cf[j][3] - M1);
        gs0 += cf[j][0] + cf[j][1];
        gs1 += cf[j][2] + cf[j][3];
    }
    gs0 += __shfl_xor_sync(0xffffffffu, gs0, 1);
    gs0 += __shfl_xor_sync(0xffffffffu, gs0, 2);
    gs1 += __shfl_xor_sync(0xffffffffu, gs1, 1);
    gs1 += __shfl_xor_sync(0xffffffffu, gs1, 2);
    if ((lane & 3) == 0) { sSum[half * 64 + r0] = gs0; sSum[half * 64 + r1] = gs1; }

    // local softmax (half 1: tiles j=2..13 are local region n>=128)
    if (half == 1) {
        float lm0 = -1e30f, lm1 = -1e30f;
        #pragma unroll
        for (int j = 2; j < 14; ++j) {
            const int c0 = (14 + j) * 8 + (lane & 3) * 2 - 128;  // local key of elems 0/2
            const int c1 = c0 + 1;
            if ((unsigned)(c0 - r0) > 15u) cf[j][0] = -1e30f;
            if ((unsigned)(c1 - r0) > 15u) cf[j][1] = -1e30f;
            if ((unsigned)(c0 - r1) > 15u) cf[j][2] = -1e30f;
            if ((unsigned)(c1 - r1) > 15u) cf[j][3] = -1e30f;
            lm0 = fmaxf(lm0, fmaxf(cf[j][0], cf[j][1]));
            lm1 = fmaxf(lm1, fmaxf(cf[j][2], cf[j][3]));
        }
        lm0 = fmaxf(lm0, __shfl_xor_sync(0xffffffffu, lm0, 1));
        lm0 = fmaxf(lm0, __shfl_xor_sync(0xffffffffu, lm0, 2));
        lm1 = fmaxf(lm1, __shfl_xor_sync(0xffffffffu, lm1, 1));
        lm1 = fmaxf(lm1, __shfl_xor_sync(0xffffffffu, lm1, 2));
        float ls0 = 0.f, ls1 = 0.f;
        #pragma unroll
        for (int j = 2; j < 14; ++j) {
            cf[j][0] = __expf(cf[j][0] - lm0); cf[j][1] = __expf(cf[j][1] - lm0);
            cf[j][2] = __expf(cf[j][2] - lm1); cf[j][3] = __expf(cf[j][3] - lm1);
            ls0 += cf[j][0] + cf[j][1];
            ls1 += cf[j][2] + cf[j][3];
        }
        ls0 += __shfl_xor_sync(0xffffffffu, ls0, 1);
        ls0 += __shfl_xor_sync(0xffffffffu, ls0, 2);
        ls1 += __shfl_xor_sync(0xffffffffu, ls1, 1);
        ls1 += __shfl_xor_sync(0xffffffffu, ls1, 2);
        const float il0 = 1.f / ls0, il1 = 1.f / ls1;
        #pragma unroll
        for (int j = 2; j < 14; ++j) {
            cf[j][0] *= il0; cf[j][1] *= il0;
            cf[j][2] *= il1; cf[j][3] *= il1;
        }
    }
    __syncthreads();
    const float iv0 = 1.f / (sSum[r0] + sSum[64 + r0]);
    const float iv1 = 1.f / (sSum[r1] + sSum[64 + r1]);
    for (int j = 0; j < jg; ++j) {
        cf[j][0] *= iv0; cf[j][1] *= iv0;
        cf[j][2] *= iv1; cf[j][3] *= iv1;
    }

    // ---- phase 2: O_partial = P @ V (bf16x3); P from frags, V trans-ldsm ----
    float of[8][4];
    #pragma unroll
    for (int nt = 0; nt < 8; ++nt)
        #pragma unroll
        for (int e = 0; e < 4; ++e) of[nt][e] = 0.f;

    const int km = (lane & 7) + ((lane >> 3) & 1) * 8;
    const uint32_t bV = sb + SVH +
        ((half * 112 + km) * KSTR + (lane >> 4) * 8) * 2;

    #pragma unroll
    for (int kc2 = 0; kc2 < 7; ++kc2) {
        const int j0 = 2 * kc2, j1 = j0 + 1;
        uint32_t ph[4], pl[4];
        ph[0] = pack_hi2(cf[j0][0], cf[j0][1]); pl[0] = pack_lo2(cf[j0][0], cf[j0][1], ph[0]);
        ph[1] = pack_hi2(cf[j0][2], cf[j0][3]); pl[1] = pack_lo2(cf[j0][2], cf[j0][3], ph[1]);
        ph[2] = pack_hi2(cf[j1][0], cf[j1][1]); pl[2] = pack_lo2(cf[j1][0], cf[j1][1], ph[2]);
        ph[3] = pack_hi2(cf[j1][2], cf[j1][3]); pl[3] = pack_lo2(cf[j1][2], cf[j1][3], ph[3]);
        #pragma unroll
        for (int nd2 = 0; nd2 < 4; ++nd2) {
            uint32_t vh4[4], vl4[4];
            const uint32_t ad = bV + (kc2 * 16 * KSTR + nd2 * 16) * 2;
            ldsm_x4_t(vh4, ad);
            ldsm_x4_t(vl4, ad + (SVL - SVH));
            mma_bf16(of[2 * nd2],     ph, vh4 + 0);
            mma_bf16(of[2 * nd2],     ph, vl4 + 0);
            mma_bf16(of[2 * nd2],     pl, vh4 + 0);
            mma_bf16(of[2 * nd2 + 1], ph, vh4 + 2);
            mma_bf16(of[2 * nd2 + 1], ph, vl4 + 2);
            mma_bf16(of[2 * nd2 + 1], pl, vh4 + 2);
        }
    }

    // ---- reduce halves via smem (reuses dead K region) ----
    float* sO = (float*)(sm + SO);   // [half][mtile][16][64]
    const int rl = lane >> 2, cb = (lane & 3) * 2;
    const int base0 = ((half * 4 + mtile) * 16 + rl) * 64;
    #pragma unroll
    for (int nt = 0; nt < 8; ++nt) {
        sO[base0 + nt * 8 + cb]     = of[nt][0];
        sO[base0 + nt * 8 + cb + 1] = of[nt][1];
        sO[base0 + 8 * 64 + nt * 8 + cb]     = of[nt][2];
        sO[base0 + 8 * 64 + nt * 8 + cb + 1] = of[nt][3];
    }
    __syncthreads();

    const int qi = tid >> 2, cg = (tid & 3) * 16;
    #pragma unroll
    for (int i = 0; i < 4; ++i) {
        const int c = cg + i * 4;
        const float4 a = *(float4*)&sO[qi * 64 + c];
        const float4 bq = *(float4*)&sO[(64 + qi) * 64 + c];
        float4 o = make_float4(a.x + bq.x, a.y + bq.y, a.z + bq.z, a.w + bq.w);
        uint2 hi, lo; cvt8(o, hi, lo);
        const size_t off = (baseBT + t0 + qi) * DD + hoff + c;
        *(uint2*)&oh[off] = hi;
        *(uint2*)&ol[off] = lo;
    }
}

// ---------------------------------------------------------------------------
extern "C" void kernel_launch(void* const* d_in, const int* in_sizes, int n_in,
                              void* d_out, int out_size)
{
    const float* x      = (const float*)d_in[0];
    const float* w_qkv  = (const float*)d_in[1];
    const float* w_proj = (const float*)d_in[2];
    const float* b_proj = (const float*)d_in[3];
    float* out = (float*)d_out;

    float* qkv;
    __nv_bfloat16 *xh, *xl, *wqh, *wql, *wph, *wpl, *ath, *atl;
    cudaGetSymbolAddress((void**)&qkv, g_qkv);
    cudaGetSymbolAddress((void**)&xh,  g_xh);
    cudaGetSymbolAddress((void**)&xl,  g_xl);
    cudaGetSymbolAddress((void**)&wqh, g_wqh);
    cudaGetSymbolAddress((void**)&wql, g_wql);
    cudaGetSymbolAddress((void**)&wph, g_wph);
    cudaGetSymbolAddress((void**)&wpl, g_wpl);
    cudaGetSymbolAddress((void**)&ath, g_ath);
    cudaGetSymbolAddress((void**)&atl, g_atl);

    const int M = BB * TT;  // 4096

    cudaFuncSetAttribute(gemm_bf16x3, cudaFuncAttributeMaxDynamicSharedMemorySize, GEMM_SMEM);
    cudaFuncSetAttribute(attn_mma, cudaFuncAttributeMaxDynamicSharedMemorySize, ATTN_SMEM);

    // 0) split inputs/weights into bf16 hi/lo
    cvt_hilo<<<512, 256>>>(x,      xh,  xl,  M * DD / 4);
    cvt_hilo<<<512, 256>>>(w_qkv,  wqh, wql, DD * D3 / 4);
    cvt_hilo<<<512, 256>>>(w_proj, wph, wpl, DD * DD / 4);

    // 1) qkv = x @ w_qkv
    gemm_bf16x3<<<dim3(D3 / 256, M / 128), 256, GEMM_SMEM>>>(
        xh, xl, wqh, wql, qkv, M, D3, DD, nullptr);

    // 2) tensor-core sparse attention (emits bf16 hi/lo)
    attn_mma<<<dim3(TT / 64, HH, BB), 256, ATTN_SMEM>>>(qkv, ath, atl);

    // 3) out = attn @ w_proj + b_proj
    gemm_bf16x3<<<dim3(DD / 256, M / 128), 256, GEMM_SMEM>>>(
        ath, atl, wph, wpl, out, M, DD, DD, b_proj);
}

// round 9
// speedup vs baseline: 3.0652x; 1.0538x over previous
#include <cuda_runtime.h>
#include <cuda_bf16.h>
#include <cstdint>
#include <cstddef>

// Problem constants
#define BB 2
#define TT 2048
#define DD 1024
#define HH 16
#define HD 64
#define D3 3072

// Scratch (allocation-free rule: __device__ globals)
__device__ __nv_bfloat16 g_qkvh[(size_t)BB * TT * D3];
__device__ __nv_bfloat16 g_qkvl[(size_t)BB * TT * D3];
__device__ __nv_bfloat16 g_xh[(size_t)BB * TT * DD];
__device__ __nv_bfloat16 g_xl[(size_t)BB * TT * DD];
__device__ __nv_bfloat16 g_wqh[(size_t)DD * D3];
__device__ __nv_bfloat16 g_wql[(size_t)DD * D3];
__device__ __nv_bfloat16 g_wph[(size_t)DD * DD];
__device__ __nv_bfloat16 g_wpl[(size_t)DD * DD];
__device__ __nv_bfloat16 g_ath[(size_t)BB * TT * DD];
__device__ __nv_bfloat16 g_atl[(size_t)BB * TT * DD];

// ---------------------------------------------------------------------------
// helpers
// ---------------------------------------------------------------------------
__device__ __forceinline__ uint32_t smem_u32(const void* p) {
    uint32_t a;
    asm("{ .reg .u64 t; cvta.to.shared.u64 t, %1; cvt.u32.u64 %0, t; }"
        : "=r"(a) : "l"(p));
    return a;
}
__device__ __forceinline__ void ldsm_x4(uint32_t* r, uint32_t addr) {
    asm volatile("ldmatrix.sync.aligned.m8n8.x4.shared.b16 {%0,%1,%2,%3}, [%4];"
                 : "=r"(r[0]), "=r"(r[1]), "=r"(r[2]), "=r"(r[3]) : "r"(addr));
}
__device__ __forceinline__ void ldsm_x4_t(uint32_t* r, uint32_t addr) {
    asm volatile("ldmatrix.sync.aligned.m8n8.x4.trans.shared.b16 {%0,%1,%2,%3}, [%4];"
                 : "=r"(r[0]), "=r"(r[1]), "=r"(r[2]), "=r"(r[3]) : "r"(addr));
}
__device__ __forceinline__ void mma_bf16(float* d, const uint32_t* a, const uint32_t* b) {
    asm volatile("mma.sync.aligned.m16n8k16.row.col.f32.bf16.bf16.f32 "
                 "{%0,%1,%2,%3}, {%4,%5,%6,%7}, {%8,%9}, {%0,%1,%2,%3};"
                 : "+f"(d[0]), "+f"(d[1]), "+f"(d[2]), "+f"(d[3])
                 : "r"(a[0]), "r"(a[1]), "r"(a[2]), "r"(a[3]),
                   "r"(b[0]), "r"(b[1]));
}
__device__ __forceinline__ void cp16(uint32_t smem_dst, const void* gsrc) {
    asm volatile("cp.async.cg.shared.global [%0], [%1], 16;"
                 :: "r"(smem_dst), "l"(gsrc));
}
// cp.async with zero-fill: src-size=0 reads nothing, fills 16B of zeros
__device__ __forceinline__ void cp16z(uint32_t smem_dst, const void* gsrc, bool valid) {
    const int sz = valid ? 16 : 0;
    asm volatile("cp.async.cg.shared.global [%0], [%1], 16, %2;"
                 :: "r"(smem_dst), "l"(gsrc), "r"(sz));
}
__device__ __forceinline__ void cp_commit() {
    asm volatile("cp.async.commit_group;" ::: "memory");
}
template <int N>
__device__ __forceinline__ void cp_wait() {
    asm volatile("cp.async.wait_group %0;" :: "n"(N) : "memory");
}
__device__ __forceinline__ void cvt8(const float4 v, uint2& hi, uint2& lo) {
    __nv_bfloat162 h0 = __floats2bfloat162_rn(v.x, v.y);
    __nv_bfloat162 h1 = __floats2bfloat162_rn(v.z, v.w);
    __nv_bfloat162 l0 = __floats2bfloat162_rn(v.x - __bfloat162float(h0.x),
                                              v.y - __bfloat162float(h0.y));
    __nv_bfloat162 l1 = __floats2bfloat162_rn(v.z - __bfloat162float(h1.x),
                                              v.w - __bfloat162float(h1.y));
    hi.x = *(uint32_t*)&h0; hi.y = *(uint32_t*)&h1;
    lo.x = *(uint32_t*)&l0; lo.y = *(uint32_t*)&l1;
}
__device__ __forceinline__ uint32_t pack_hi2(float a, float b) {
    __nv_bfloat162 t = __floats2bfloat162_rn(a, b);
    return *(uint32_t*)&t;
}
__device__ __forceinline__ uint32_t pack_lo2(float a, float b, uint32_t hi) {
    __nv_bfloat162 h = *(__nv_bfloat162*)&hi;
    __nv_bfloat162 t = __floats2bfloat162_rn(a - __bfloat162float(h.x),
                                             b - __bfloat162float(h.y));
    return *(uint32_t*)&t;
}

// ---------------------------------------------------------------------------
// fp32 -> (bf16 hi, bf16 lo) conversion
// ---------------------------------------------------------------------------
__global__ __launch_bounds__(256)
void cvt_hilo(const float* __restrict__ in, __nv_bfloat16* __restrict__ hi,
              __nv_bfloat16* __restrict__ lo, int n4)
{
    const int stride = gridDim.x * blockDim.x;
    for (int i = blockIdx.x * blockDim.x + threadIdx.x; i < n4; i += stride) {
        const float4 v = ((const float4*)in)[i];
        uint2 h, l;
        cvt8(v, h, l);
        ((uint2*)hi)[i] = h;
        ((uint2*)lo)[i] = l;
    }
}

// ---------------------------------------------------------------------------
// bf16-split GEMM: optionally writes fp32 C, or bf16 hi/lo pair (Ch/Cl).
// ---------------------------------------------------------------------------
#define A_STRIDE 40
#define B_STRIDE 264
#define A_BYTES  (128 * A_STRIDE * 2)
#define B_BYTES  (32 * B_STRIDE * 2)
#define OFF_AL   A_BYTES
#define OFF_BH   (2 * A_BYTES)
#define OFF_BL   (2 * A_BYTES + B_BYTES)
#define STAGE_BYTES (2 * A_BYTES + 2 * B_BYTES)
#define NSTAGE 4
#define GEMM_SMEM (NSTAGE * STAGE_BYTES)

__global__ __launch_bounds__(256, 1)
void gemm_bf16x3(const __nv_bfloat16* __restrict__ Ah, const __nv_bfloat16* __restrict__ Al,
                 const __nv_bfloat16* __restrict__ Bh, const __nv_bfloat16* __restrict__ Bl,
                 float* __restrict__ C,
                 __nv_bfloat16* __restrict__ Ch, __nv_bfloat16* __restrict__ Cl,
                 int M, int N, int K,
                 const float* __restrict__ bias)
{
    extern __shared__ char sm[];
    const uint32_t sb = smem_u32(sm);
    const int tid = threadIdx.x;
    const int lane = tid & 31, wid = tid >> 5;
    const int wm = wid & 1, wn = wid >> 1;
    const int m0 = blockIdx.y * 128, n0 = blockIdx.x * 256;
    const int NC = K >> 5;

    const int arow = tid >> 2, aseg = tid & 3;
    const int brow = tid >> 5, bseg = tid & 31;

    const __nv_bfloat16* gAh = Ah + (size_t)(m0 + arow) * K + aseg * 8;
    const __nv_bfloat16* gAl = Al + (size_t)(m0 + arow) * K + aseg * 8;
    const __nv_bfloat16* gBh = Bh + (size_t)brow * N + n0 + bseg * 8;
    const __nv_bfloat16* gBl = Bl + (size_t)brow * N + n0 + bseg * 8;
    const uint32_t dA = arow * (A_STRIDE * 2) + aseg * 16;
    const uint32_t dB = brow * (B_STRIDE * 2) + bseg * 16;

    float acc[4][8][4];
    #pragma unroll
    for (int mt = 0; mt < 4; ++mt)
        #pragma unroll
        for (int nt = 0; nt < 8; ++nt)
            #pragma unroll
            for (int q = 0; q < 4; ++q) acc[mt][nt][q] = 0.f;

    auto issue = [&](int cc, int st) {
        const uint32_t stb = sb + (uint32_t)st * STAGE_BYTES;
        const size_t ka = (size_t)cc * 32;
        #pragma unroll
        for (int i = 0; i < 2; ++i) {
            cp16(stb + dA + i * 64 * (A_STRIDE * 2),          gAh + ka + (size_t)i * 64 * K);
            cp16(stb + OFF_AL + dA + i * 64 * (A_STRIDE * 2), gAl + ka + (size_t)i * 64 * K);
        }
        const size_t kb = (size_t)cc * 32 * N;
        #pragma unroll
        for (int i = 0; i < 4; ++i) {
            cp16(stb + OFF_BH + dB + i * 8 * (B_STRIDE * 2), gBh + kb + (size_t)i * 8 * N);
            cp16(stb + OFF_BL + dB + i * 8 * (B_STRIDE * 2), gBl + kb + (size_t)i * 8 * N);
        }
        cp_commit();
    };

    issue(0, 0);
    if (NC > 1) issue(1, 1);
    if (NC > 2) issue(2, 2);

    const uint32_t aRow = ((wm * 64 + (lane & 15)) * A_STRIDE + (lane >> 4) * 8) * 2;
    const int km = (lane & 7) + ((lane >> 3) & 1) * 8;
    const uint32_t bCol = OFF_BH + (km * B_STRIDE + wn * 64 + (lane >> 4) * 8) * 2;

    for (int c = 0; c < NC; ++c) {
        if (c + 2 < NC) cp_wait<2>();
        else if (c + 1 < NC) cp_wait<1>();
        else cp_wait<0>();
        __syncthreads();
        if (c + 3 < NC) issue(c + 3, (c + 3) & 3);

        const uint32_t stb = sb + (uint32_t)(c & 3) * STAGE_BYTES;
        #pragma unroll
        for (int ks = 0; ks < 2; ++ks) {
            const int k0 = ks * 16;
            uint32_t ahr[4][4], alr[4][4];
            #pragma unroll
            for (int mt = 0; mt < 4; ++mt) {
                ldsm_x4(ahr[mt], stb + aRow + (mt * 16 * A_STRIDE + k0) * 2);
                ldsm_x4(alr[mt], stb + OFF_AL + aRow + (mt * 16 * A_STRIDE + k0) * 2);
            }
            uint32_t bh[16], bl[16];
            #pragma unroll
            for (int j = 0; j < 4; ++j) {
                ldsm_x4_t(bh + j * 4, stb + bCol + (k0 * B_STRIDE + j * 16) * 2);
                ldsm_x4_t(bl + j * 4, stb + B_BYTES + bCol + (k0 * B_STRIDE + j * 16) * 2);
            }
            #pragma unroll
            for (int mt = 0; mt < 4; ++mt)
                #pragma unroll
                for (int nt = 0; nt < 8; ++nt) {
                    mma_bf16(acc[mt][nt], ahr[mt], bh + nt * 2);
                    mma_bf16(acc[mt][nt], ahr[mt], bl + nt * 2);
                    mma_bf16(acc[mt][nt], alr[mt], bh + nt * 2);
                }
        }
    }

    const int row = m0 + wm * 64 + (lane >> 2);
    const int colb = n0 + wn * 64 + (lane & 3) * 2;
    #pragma unroll
    for (int nt = 0; nt < 8; ++nt) {
        float2 bv = make_float2(0.f, 0.f);
        if (bias) bv = *(const float2*)(bias + colb + nt * 8);
        #pragma unroll
        for (int mt = 0; mt < 4; ++mt) {
            const float* d = acc[mt][nt];
            const float v00 = d[0] + bv.x, v01 = d[1] + bv.y;
            const float v10 = d[2] + bv.x, v11 = d[3] + bv.y;
            const size_t i0 = (size_t)(row + mt * 16) * N + colb + nt * 8;
            const size_t i1 = (size_t)(row + mt * 16 + 8) * N + colb + nt * 8;
            if (Ch) {
                uint32_t h0 = pack_hi2(v00, v01), l0 = pack_lo2(v00, v01, h0);
                uint32_t h1 = pack_hi2(v10, v11), l1 = pack_lo2(v10, v11, h1);
                *(uint32_t*)&Ch[i0] = h0; *(uint32_t*)&Cl[i0] = l0;
                *(uint32_t*)&Ch[i1] = h1; *(uint32_t*)&Cl[i1] = l1;
            } else {
                *(float2*)&C[i0] = make_float2(v00, v01);
                *(float2*)&C[i1] = make_float2(v10, v11);
            }
        }
    }
}

// ---------------------------------------------------------------------------
// Tensor-core sparse attention; stages pre-split bf16 hi/lo qkv via cp.async
// (zero-fill for pad rows). Block = (b, h, 64-query tile), 8 warps.
// ---------------------------------------------------------------------------
#define KSTR 72
#define SQH 0
#define SQL (64 * KSTR * 2)
#define SKH (2 * 64 * KSTR * 2)
#define SKL (SKH + 224 * KSTR * 2)
#define SVH (SKL + 224 * KSTR * 2)
#define SVL (SVH + 224 * KSTR * 2)
#define SRED (SVL + 224 * KSTR * 2)
#define SO  SKH
#define ATTN_SMEM (SRED + 1024)

__global__ __launch_bounds__(256, 1)
void attn_mma(const __nv_bfloat16* __restrict__ qh_, const __nv_bfloat16* __restrict__ ql_,
              __nv_bfloat16* __restrict__ oh, __nv_bfloat16* __restrict__ ol)
{
    const int t0 = blockIdx.x * 64;
    const int h  = blockIdx.y;
    const int b  = blockIdx.z;
    const int tid = threadIdx.x;
    const int lane = tid & 31, wid = tid >> 5;
    const int mtile = wid & 3, half = wid >> 2;

    extern __shared__ char sm[];
    const uint32_t sb = smem_u32(sm);
    const size_t baseBT = (size_t)b * TT;
    const int hoff = h * HD;

    // ---- stage Q (64 rows x 8 chunks) ----
    for (int idx = tid; idx < 64 * 8; idx += 256) {
        const int r = idx >> 3, c = (idx & 7) * 8;
        const size_t go = (baseBT + t0 + r) * D3 + hoff + c;
        const uint32_t off = (r * KSTR + c) * 2;
        cp16(sb + SQH + off, qh_ + go);
        cp16(sb + SQL + off, ql_ + go);
    }
    // ---- stage K/V (224 rows x 8 chunks), zero-fill invalid rows ----
    for (int idx = tid; idx < 224 * 8; idx += 256) {
        const int r = idx >> 3, c = (idx & 7) * 8;
        int t = 0; bool valid = false;
        if (r < 128)      { t = r * 16;              valid = true; }
        else if (r < 207) { t = t0 - 15 + (r - 128); valid = (t >= 0); }
        if (t < 0) t = 0;
        const size_t go = (baseBT + t) * D3 + hoff + c;
        const uint32_t off = (r * KSTR + c) * 2;
        cp16z(sb + SKH + off, qh_ + go + 1024, valid);
        cp16z(sb + SKL + off, ql_ + go + 1024, valid);
        cp16z(sb + SVH + off, qh_ + go + 2048, valid);
        cp16z(sb + SVL + off, ql_ + go + 2048, valid);
    }
    cp_commit();
    cp_wait<0>();
    __syncthreads();

    // ---- phase 1: S = Q @ K^T (bf16x3) ----
    uint32_t qh[4][4], ql[4][4];
    const uint32_t aQ = sb + SQH + ((mtile * 16 + (lane & 15)) * KSTR + (lane >> 4) * 8) * 2;
    #pragma unroll
    for (int kc = 0; kc < 4; ++kc) {
        ldsm_x4(qh[kc], aQ + kc * 32);
        ldsm_x4(ql[kc], aQ + (SQL - SQH) + kc * 32);
    }

    const uint32_t bK = sb + SKH +
        ((half * 112 + (lane & 7) + ((lane >> 4) & 1) * 8) * KSTR + ((lane >> 3) & 1) * 8) * 2;

    float cf[14][4];
    #pragma unroll
    for (int j = 0; j < 14; ++j)
        #pragma unroll
        for (int e = 0; e < 4; ++e) cf[j][e] = 0.f;

    #pragma unroll
    for (int jj = 0; jj < 7; ++jj) {
        #pragma unroll
        for (int kc = 0; kc < 4; ++kc) {
            uint32_t kh4[4], kl4[4];
            const uint32_t ad = bK + (jj * 16 * KSTR + kc * 16) * 2;
            ldsm_x4(kh4, ad);
            ldsm_x4(kl4, ad + (SKL - SKH));
            mma_bf16(cf[2 * jj],     qh[kc], kh4 + 0);
            mma_bf16(cf[2 * jj],     qh[kc], kl4 + 0);
            mma_bf16(cf[2 * jj],     ql[kc], kh4 + 0);
            mma_bf16(cf[2 * jj + 1], qh[kc], kh4 + 2);
            mma_bf16(cf[2 * jj + 1], qh[kc], kl4 + 2);
            mma_bf16(cf[2 * jj + 1], ql[kc], kh4 + 2);
        }
    }
    #pragma unroll
    for (int j = 0; j < 14; ++j)
        #pragma unroll
        for (int e = 0; e < 4; ++e) cf[j][e] *= 0.125f;

    // ---- softmax ----
    const int r0 = mtile * 16 + (lane >> 2);
    const int r1 = r0 + 8;
    float* sMax = (float*)(sm + SRED);
    float* sSum = (float*)(sm + SRED + 512);
    const int jg = (half == 0) ? 14 : 2;

    float gm0 = -1e30f, gm1 = -1e30f;
    for (int j = 0; j < jg; ++j) {
        gm0 = fmaxf(gm0, fmaxf(cf[j][0], cf[j][1]));
        gm1 = fmaxf(gm1, fmaxf(cf[j][2], cf[j][3]));
    }
    gm0 = fmaxf(gm0, __shfl_xor_sync(0xffffffffu, gm0, 1));
    gm0 = fmaxf(gm0, __shfl_xor_sync(0xffffffffu, gm0, 2));
    gm1 = fmaxf(gm1, __shfl_xor_sync(0xffffffffu, gm1, 1));
    gm1 = fmaxf(gm1, __shfl_xor_sync(0xffffffffu, gm1, 2));
    if ((lane & 3) == 0) { sMax[half * 64 + r0] = gm0; sMax[half * 64 + r1] = gm1; }
    __syncthreads();
    const float M0 = fmaxf(sMax[r0], sMax[64 + r0]);
    const float M1 = fmaxf(sMax[r1], sMax[64 + r1]);

    float gs0 = 0.f, gs1 = 0.f;
    for (int j = 0; j < jg; ++j) {
        cf[j][0] = __expf(cf[j][0] - M0); cf[j][1] = __expf(cf[j][1] - M0);
        cf[j][2] = __expf(cf[j][2] - M1); cf[j][3] = __expf(cf[j][3] - M1);
        gs0 += cf[j][0] + cf[j][1];
        gs1 += cf[j][2] + cf[j][3];
    }
    gs0 += __shfl_xor_sync(0xffffffffu, gs0, 1);
    gs0 += __shfl_xor_sync(0xffffffffu, gs0, 2);
    gs1 += __shfl_xor_sync(0xffffffffu, gs1, 1);
    gs1 += __shfl_xor_sync(0xffffffffu, gs1, 2);
    if ((lane & 3) == 0) { sSum[half * 64 + r0] = gs0; sSum[half * 64 + r1] = gs1; }

    if (half == 1) {
        float lm0 = -1e30f, lm1 = -1e30f;
        #pragma unroll
        for (int j = 2; j < 14; ++j) {
            const int c0 = (14 + j) * 8 + (lane & 3) * 2 - 128;
            const int c1 = c0 + 1;
            if ((unsigned)(c0 - r0) > 15u) cf[j][0] = -1e30f;
            if ((unsigned)(c1 - r0) > 15u) cf[j][1] = -1e30f;
            if ((unsigned)(c0 - r1) > 15u) cf[j][2] = -1e30f;
            if ((unsigned)(c1 - r1) > 15u) cf[j][3] = -1e30f;
            lm0 = fmaxf(lm0, fmaxf(cf[j][0], cf[j][1]));
            lm1 = fmaxf(lm1, fmaxf(cf[j][2], cf[j][3]));
        }
        lm0 = fmaxf(lm0, __shfl_xor_sync(0xffffffffu, lm0, 1));
        lm0 = fmaxf(lm0, __shfl_xor_sync(0xffffffffu, lm0, 2));
        lm1 = fmaxf(lm1, __shfl_xor_sync(0xffffffffu, lm1, 1));
        lm1 = fmaxf(lm1, __shfl_xor_sync(0xffffffffu, lm1, 2));
        float ls0 = 0.f, ls1 = 0.f;
        #pragma unroll
        for (int j = 2; j < 14; ++j) {
            cf[j][0] = __expf(cf[j][0] - lm0); cf[j][1] = __expf(cf[j][1] - lm0);
            cf[j][2] = __expf(cf[j][2] - lm1); cf[j][3] = __expf(cf[j][3] - lm1);
            ls0 += cf[j][0] + cf[j][1];
            ls1 += cf[j][2] + cf[j][3];
        }
        ls0 += __shfl_xor_sync(0xffffffffu, ls0, 1);
        ls0 += __shfl_xor_sync(0xffffffffu, ls0, 2);
        ls1 += __shfl_xor_sync(0xffffffffu, ls1, 1);
        ls1 += __shfl_xor_sync(0xffffffffu, ls1, 2);
        const float il0 = 1.f / ls0, il1 = 1.f / ls1;
        #pragma unroll
        for (int j = 2; j < 14; ++j) {
            cf[j][0] *= il0; cf[j][1] *= il0;
            cf[j][2] *= il1; cf[j][3] *= il1;
        }
    }
    __syncthreads();
    const float iv0 = 1.f / (sSum[r0] + sSum[64 + r0]);
    const float iv1 = 1.f / (sSum[r1] + sSum[64 + r1]);
    for (int j = 0; j < jg; ++j) {
        cf[j][0] *= iv0; cf[j][1] *= iv0;
        cf[j][2] *= iv1; cf[j][3] *= iv1;
    }

    // ---- phase 2: O_partial = P @ V ----
    float of[8][4];
    #pragma unroll
    for (int nt = 0; nt < 8; ++nt)
        #pragma unroll
        for (int e = 0; e < 4; ++e) of[nt][e] = 0.f;

    const int km = (lane & 7) + ((lane >> 3) & 1) * 8;
    const uint32_t bV = sb + SVH + ((half * 112 + km) * KSTR + (lane >> 4) * 8) * 2;

    #pragma unroll
    for (int kc2 = 0; kc2 < 7; ++kc2) {
        const int j0 = 2 * kc2, j1 = j0 + 1;
        uint32_t ph[4], pl[4];
        ph[0] = pack_hi2(cf[j0][0], cf[j0][1]); pl[0] = pack_lo2(cf[j0][0], cf[j0][1], ph[0]);
        ph[1] = pack_hi2(cf[j0][2], cf[j0][3]); pl[1] = pack_lo2(cf[j0][2], cf[j0][3], ph[1]);
        ph[2] = pack_hi2(cf[j1][0], cf[j1][1]); pl[2] = pack_lo2(cf[j1][0], cf[j1][1], ph[2]);
        ph[3] = pack_hi2(cf[j1][2], cf[j1][3]); pl[3] = pack_lo2(cf[j1][2], cf[j1][3], ph[3]);
        #pragma unroll
        for (int nd2 = 0; nd2 < 4; ++nd2) {
            uint32_t vh4[4], vl4[4];
            const uint32_t ad = bV + (kc2 * 16 * KSTR + nd2 * 16) * 2;
            ldsm_x4_t(vh4, ad);
            ldsm_x4_t(vl4, ad + (SVL - SVH));
            mma_bf16(of[2 * nd2],     ph, vh4 + 0);
            mma_bf16(of[2 * nd2],     ph, vl4 + 0);
            mma_bf16(of[2 * nd2],     pl, vh4 + 0);
            mma_bf16(of[2 * nd2 + 1], ph, vh4 + 2);
            mma_bf16(of[2 * nd2 + 1], ph, vl4 + 2);
            mma_bf16(of[2 * nd2 + 1], pl, vh4 + 2);
        }
    }

    // ---- reduce halves via smem ----
    float* sO = (float*)(sm + SO);
    const int rl = lane >> 2, cb = (lane & 3) * 2;
    const int base0 = ((half * 4 + mtile) * 16 + rl) * 64;
    #pragma unroll
    for (int nt = 0; nt < 8; ++nt) {
        sO[base0 + nt * 8 + cb]     = of[nt][0];
        sO[base0 + nt * 8 + cb + 1] = of[nt][1];
        sO[base0 + 8 * 64 + nt * 8 + cb]     = of[nt][2];
        sO[base0 + 8 * 64 + nt * 8 + cb + 1] = of[nt][3];
    }
    __syncthreads();

    const int qi = tid >> 2, cg = (tid & 3) * 16;
    #pragma unroll
    for (int i = 0; i < 4; ++i) {
        const int c = cg + i * 4;
        const float4 a = *(float4*)&sO[qi * 64 + c];
        const float4 bq = *(float4*)&sO[(64 + qi) * 64 + c];
        float4 o = make_float4(a.x + bq.x, a.y + bq.y, a.z + bq.z, a.w + bq.w);
        uint2 hi, lo; cvt8(o, hi, lo);
        const size_t off = (baseBT + t0 + qi) * DD + hoff + c;
        *(uint2*)&oh[off] = hi;
        *(uint2*)&ol[off] = lo;
    }
}

// ---------------------------------------------------------------------------
extern "C" void kernel_launch(void* const* d_in, const int* in_sizes, int n_in,
                              void* d_out, int out_size)
{
    const float* x      = (const float*)d_in[0];
    const float* w_qkv  = (const float*)d_in[1];
    const float* w_proj = (const float*)d_in[2];
    const float* b_proj = (const float*)d_in[3];
    float* out = (float*)d_out;

    __nv_bfloat16 *qkvh, *qkvl, *xh, *xl, *wqh, *wql, *wph, *wpl, *ath, *atl;
    cudaGetSymbolAddress((void**)&qkvh, g_qkvh);
    cudaGetSymbolAddress((void**)&qkvl, g_qkvl);
    cudaGetSymbolAddress((void**)&xh,  g_xh);
    cudaGetSymbolAddress((void**)&xl,  g_xl);
    cudaGetSymbolAddress((void**)&wqh, g_wqh);
    cudaGetSymbolAddress((void**)&wql, g_wql);
    cudaGetSymbolAddress((void**)&wph, g_wph);
    cudaGetSymbolAddress((void**)&wpl, g_wpl);
    cudaGetSymbolAddress((void**)&ath, g_ath);
    cudaGetSymbolAddress((void**)&atl, g_atl);

    const int M = BB * TT;  // 4096

    cudaFuncSetAttribute(gemm_bf16x3, cudaFuncAttributeMaxDynamicSharedMemorySize, GEMM_SMEM);
    cudaFuncSetAttribute(attn_mma, cudaFuncAttributeMaxDynamicSharedMemorySize, ATTN_SMEM);

    // 0) split inputs/weights into bf16 hi/lo
    cvt_hilo<<<512, 256>>>(x,      xh,  xl,  M * DD / 4);
    cvt_hilo<<<512, 256>>>(w_qkv,  wqh, wql, DD * D3 / 4);
    cvt_hilo<<<512, 256>>>(w_proj, wph, wpl, DD * DD / 4);

    // 1) qkv = x @ w_qkv  (emitted directly as bf16 hi/lo)
    gemm_bf16x3<<<dim3(D3 / 256, M / 128), 256, GEMM_SMEM>>>(
        xh, xl, wqh, wql, nullptr, qkvh, qkvl, M, D3, DD, nullptr);

    // 2) tensor-core sparse attention (consumes + emits bf16 hi/lo)
    attn_mma<<<dim3(TT / 64, HH, BB), 256, ATTN_SMEM>>>(qkvh, qkvl, ath, atl);

    // 3) out = attn @ w_proj + b_proj (fp32 out)
    gemm_bf16x3<<<dim3(DD / 256, M / 128), 256, GEMM_SMEM>>>(
        ath, atl, wph, wpl, out, nullptr, nullptr, M, DD, DD, b_proj);
}